// round 1
// baseline (speedup 1.0000x reference)
#include <cuda_runtime.h>
#include <math.h>

// Problem constants
#define BB    64
#define NTOK  64
#define MTOK  64
#define CC    512
#define HH    8
#define HD    64
#define FREQE 256
#define ROWS  4096   // B*N == N*M

// Scratch (device globals; no allocation allowed)
__device__ float g_emb[ROWS * FREQE];
__device__ float g_hid[ROWS * CC];
__device__ float g_pe [ROWS * CC];   // row (n*64+m), col (h*64+d)
__device__ float g_q  [ROWS * CC];   // row (b*64+n), col (h*64+d)
__device__ float g_k  [ROWS * CC];
__device__ float g_v  [ROWS * CC];
__device__ float g_x  [ROWS * CC];

// ---------------------------------------------------------------------------
// Sinusoidal embedding: emb[p, j] = cos/sin(t_p * f_{j mod 128})
// ---------------------------------------------------------------------------
__global__ __launch_bounds__(256) void embed_kernel(const float* __restrict__ qpos) {
    int idx = blockIdx.x * blockDim.x + threadIdx.x;   // 0 .. 4096*256-1
    int p = idx >> 8;
    int j = idx & 255;
    float t = qpos[p];
    int jj = j & 127;
    float f = expf(-9.210340371976184f * (float)jj * (1.0f / 128.0f));
    float a = t * f;
    g_emb[idx] = (j < 128) ? cosf(a) : sinf(a);
}

// ---------------------------------------------------------------------------
// FP32 SGEMM: C[M,N] = A[M,K] @ W[K,N] (+bias) (+SiLU | +residual)
// BM=BN=128, BK=8, 256 threads, 8x8 per thread.
// epi: 0 = bias only, 1 = bias+SiLU, 2 = bias+residual
// ---------------------------------------------------------------------------
__global__ __launch_bounds__(256) void sgemm128(
    const float* __restrict__ A, const float* __restrict__ Wt,
    const float* __restrict__ bias, const float* __restrict__ resid,
    float* __restrict__ Cout, int M, int N, int K, int epi)
{
    __shared__ float As[8][128];
    __shared__ float Bs[8][128];

    int t  = threadIdx.x;
    int tx = t & 15;          // 0..15 -> output cols tx*8..tx*8+7
    int ty = t >> 4;          // 0..15 -> output rows ty*8..ty*8+7
    int m0 = blockIdx.y * 128;
    int n0 = blockIdx.x * 128;

    float acc[8][8];
#pragma unroll
    for (int i = 0; i < 8; i++)
#pragma unroll
        for (int j = 0; j < 8; j++) acc[i][j] = 0.0f;

    int ar = t >> 1;            // 0..127
    int ac = (t & 1) * 4;       // 0 or 4
    int br = t >> 5;            // 0..7
    int bc = (t & 31) * 4;      // 0..124

    const float* Aptr = A  + (size_t)(m0 + ar) * K + ac;
    const float* Wptr = Wt + (size_t)br * N + n0 + bc;

    for (int k0 = 0; k0 < K; k0 += 8) {
        float4 va = *(const float4*)(Aptr + k0);
        float4 vb = *(const float4*)(Wptr + (size_t)k0 * N);
        As[ac + 0][ar] = va.x;
        As[ac + 1][ar] = va.y;
        As[ac + 2][ar] = va.z;
        As[ac + 3][ar] = va.w;
        *(float4*)&Bs[br][bc] = vb;
        __syncthreads();

#pragma unroll
        for (int kk = 0; kk < 8; kk++) {
            float4 a0 = *(const float4*)&As[kk][ty * 8];
            float4 a1 = *(const float4*)&As[kk][ty * 8 + 4];
            float4 b0 = *(const float4*)&Bs[kk][tx * 8];
            float4 b1 = *(const float4*)&Bs[kk][tx * 8 + 4];
            float ra[8] = {a0.x, a0.y, a0.z, a0.w, a1.x, a1.y, a1.z, a1.w};
            float rb[8] = {b0.x, b0.y, b0.z, b0.w, b1.x, b1.y, b1.z, b1.w};
#pragma unroll
            for (int i = 0; i < 8; i++)
#pragma unroll
                for (int j = 0; j < 8; j++)
                    acc[i][j] = fmaf(ra[i], rb[j], acc[i][j]);
        }
        __syncthreads();
    }

    // Epilogue
#pragma unroll
    for (int i = 0; i < 8; i++) {
        int row = m0 + ty * 8 + i;
        float*       cp = Cout + (size_t)row * N + n0 + tx * 8;
        const float* rp = resid ? (resid + (size_t)row * N + n0 + tx * 8) : (const float*)0;
#pragma unroll
        for (int j = 0; j < 8; j++) {
            float v = acc[i][j];
            if (bias) v += bias[n0 + tx * 8 + j];
            if (epi == 1) v = v / (1.0f + __expf(-v));   // SiLU
            if (epi == 2) v += rp[j];                    // residual
            cp[j] = v;
        }
    }
}

// ---------------------------------------------------------------------------
// Fused attention: one block per (b,h).
// scores[n,m] = scale * sum_d q[b,n,h,d] * pe[n,m,h,d] * k[b,m,h,d]
// softmax over m, then x[b,n,h,d] = sum_m attn[m] * v[b,m,h,d]
// ---------------------------------------------------------------------------
__global__ __launch_bounds__(256) void attn_kernel() {
    int b = blockIdx.x;
    int h = blockIdx.y;

    __shared__ float ks[64][68];   // padded to kill bank conflicts
    __shared__ float vs[64][68];
    __shared__ float qrow[64];
    __shared__ float s[64];

    int t = threadIdx.x;

    // Load K, V slices [64 m][64 d] for this (b,h)
#pragma unroll
    for (int i = 0; i < 4; i++) {
        int idx4 = t + i * 256;            // float4 index, 0..1023
        int m = idx4 >> 4;                 // 0..63
        int d = (idx4 & 15) << 2;          // 0..60 step 4
        size_t off = (size_t)(b * 64 + m) * 512 + h * 64 + d;
        float4 kv = *(const float4*)(g_k + off);
        float4 vv = *(const float4*)(g_v + off);
        *(float4*)&ks[m][d] = kv;
        *(float4*)&vs[m][d] = vv;
    }
    __syncthreads();

    int m  = t >> 2;     // 0..63
    int dg = t & 3;      // 0..3 -> d chunk of 16
    const float* peb = g_pe + h * 64;

    for (int n = 0; n < 64; n++) {
        if (t < 16) {
            float4 qv = *(const float4*)(g_q + (size_t)(b * 64 + n) * 512 + h * 64 + t * 4);
            *(float4*)&qrow[t * 4] = qv;
        }
        __syncthreads();

        // scores: each group of 4 threads owns one m
        float p = 0.0f;
        const float* pep = peb + (size_t)(n * 64 + m) * 512 + dg * 16;
#pragma unroll
        for (int i = 0; i < 4; i++) {
            float4 pe4 = *(const float4*)(pep + i * 4);
            int d = dg * 16 + i * 4;
            p = fmaf(qrow[d + 0] * ks[m][d + 0], pe4.x, p);
            p = fmaf(qrow[d + 1] * ks[m][d + 1], pe4.y, p);
            p = fmaf(qrow[d + 2] * ks[m][d + 2], pe4.z, p);
            p = fmaf(qrow[d + 3] * ks[m][d + 3], pe4.w, p);
        }
        p += __shfl_xor_sync(0xffffffffu, p, 1);
        p += __shfl_xor_sync(0xffffffffu, p, 2);
        if (dg == 0) s[m] = p * 0.125f;   // scale = HD^-0.5
        __syncthreads();

        // softmax over 64 entries, warp 0
        if (t < 32) {
            float a  = s[t];
            float c2 = s[t + 32];
            float mx = fmaxf(a, c2);
#pragma unroll
            for (int off = 16; off > 0; off >>= 1)
                mx = fmaxf(mx, __shfl_xor_sync(0xffffffffu, mx, off));
            float e1 = __expf(a - mx), e2 = __expf(c2 - mx);
            float sm = e1 + e2;
#pragma unroll
            for (int off = 16; off > 0; off >>= 1)
                sm += __shfl_xor_sync(0xffffffffu, sm, off);
            float inv = 1.0f / sm;
            s[t]      = e1 * inv;
            s[t + 32] = e2 * inv;
        }
        __syncthreads();

        // x[n][d] = sum_m attn[m] * v[m][d]
        if (t < 64) {
            float xv = 0.0f;
#pragma unroll
            for (int mm = 0; mm < 64; mm++)
                xv = fmaf(s[mm], vs[mm][t], xv);
            g_x[(size_t)(b * 64 + n) * 512 + h * 64 + t] = xv;
        }
        __syncthreads();
    }
}

// ---------------------------------------------------------------------------
// Launch
// ---------------------------------------------------------------------------
extern "C" void kernel_launch(void* const* d_in, const int* in_sizes, int n_in,
                              void* d_out, int out_size)
{
    const float* query = (const float*)d_in[0];
    const float* qpos  = (const float*)d_in[1];
    const float* Wq    = (const float*)d_in[2];
    const float* bq    = (const float*)d_in[3];
    const float* Wk    = (const float*)d_in[4];
    const float* Wv    = (const float*)d_in[5];
    const float* bv    = (const float*)d_in[6];
    const float* Wo    = (const float*)d_in[7];
    const float* bo    = (const float*)d_in[8];
    const float* W1    = (const float*)d_in[9];
    const float* b1    = (const float*)d_in[10];
    const float* W2    = (const float*)d_in[11];
    const float* b2    = (const float*)d_in[12];
    float* out = (float*)d_out;

    void *p_emb, *p_hid, *p_pe, *p_q, *p_k, *p_v, *p_x;
    cudaGetSymbolAddress(&p_emb, g_emb);
    cudaGetSymbolAddress(&p_hid, g_hid);
    cudaGetSymbolAddress(&p_pe,  g_pe);
    cudaGetSymbolAddress(&p_q,   g_q);
    cudaGetSymbolAddress(&p_k,   g_k);
    cudaGetSymbolAddress(&p_v,   g_v);
    cudaGetSymbolAddress(&p_x,   g_x);

    dim3 gemm_grid(4, 32);   // N/128=4, M/128=32

    // 1) sinusoidal embedding
    embed_kernel<<<4096, 256>>>(qpos);

    // 2) pe MLP: silu(emb @ W1 + b1) @ W2 + b2
    sgemm128<<<gemm_grid, 256>>>((const float*)p_emb, W1, b1, nullptr,
                                 (float*)p_hid, ROWS, CC, FREQE, 1);
    sgemm128<<<gemm_grid, 256>>>((const float*)p_hid, W2, b2, nullptr,
                                 (float*)p_pe, ROWS, CC, CC, 0);

    // 3) q / k / v projections
    sgemm128<<<gemm_grid, 256>>>(query, Wq, bq, nullptr,
                                 (float*)p_q, ROWS, CC, CC, 0);
    sgemm128<<<gemm_grid, 256>>>(query, Wk, nullptr, nullptr,
                                 (float*)p_k, ROWS, CC, CC, 0);
    sgemm128<<<gemm_grid, 256>>>(query, Wv, bv, nullptr,
                                 (float*)p_v, ROWS, CC, CC, 0);

    // 4) fused pe-modulated attention
    attn_kernel<<<dim3(BB, HH), 256>>>();

    // 5) output projection + residual
    sgemm128<<<gemm_grid, 256>>>((const float*)p_x, Wo, bo, query,
                                 out, ROWS, CC, CC, 2);
}

// round 3
// speedup vs baseline: 1.7582x; 1.7582x over previous
#include <cuda_runtime.h>
#include <cuda_bf16.h>
#include <math.h>
#include <stdint.h>

// Problem constants
#define BB    64
#define CC    512
#define HH    8
#define HD    64
#define FREQE 256
#define ROWS  4096   // B*N == N*M

// ---------------------------------------------------------------------------
// Scratch (device globals; no allocation allowed)
// ---------------------------------------------------------------------------
__device__ float g_pe[ROWS * CC];
__device__ float g_q [ROWS * CC];
__device__ float g_k [ROWS * CC];
__device__ float g_v [ROWS * CC];

__device__ __nv_bfloat16 g_emb_h[ROWS * FREQE];
__device__ __nv_bfloat16 g_emb_l[ROWS * FREQE];
__device__ __nv_bfloat16 g_hid_h[ROWS * CC];
__device__ __nv_bfloat16 g_hid_l[ROWS * CC];
__device__ __nv_bfloat16 g_qry_h[ROWS * CC];
__device__ __nv_bfloat16 g_qry_l[ROWS * CC];
__device__ __nv_bfloat16 g_x_h [ROWS * CC];
__device__ __nv_bfloat16 g_x_l [ROWS * CC];
__device__ __nv_bfloat16 g_w_h [6 * CC * CC];   // transposed weights [N,K], hi
__device__ __nv_bfloat16 g_w_l [6 * CC * CC];   // transposed weights [N,K], lo

__device__ __forceinline__ void split_bf16(float x, __nv_bfloat16& h, __nv_bfloat16& l) {
    h = __float2bfloat16(x);
    l = __float2bfloat16(x - __bfloat162float(h));
}

// ---------------------------------------------------------------------------
// Sinusoidal embedding -> bf16 hi/lo
// ---------------------------------------------------------------------------
__global__ __launch_bounds__(256) void embed_kernel(const float* __restrict__ qpos) {
    int idx = blockIdx.x * blockDim.x + threadIdx.x;   // 0 .. 4096*256-1
    int p = idx >> 8;
    int j = idx & 255;
    float t = qpos[p];
    int jj = j & 127;
    float f = expf(-9.210340371976184f * (float)jj * (1.0f / 128.0f));
    float a = t * f;
    float v = (j < 128) ? cosf(a) : sinf(a);
    __nv_bfloat16 h, l;
    split_bf16(v, h, l);
    g_emb_h[idx] = h;
    g_emb_l[idx] = l;
}

// ---------------------------------------------------------------------------
// Weight transpose + hi/lo split: W[K,N] fp32 -> Wt[N,K] bf16 (hi,lo)
// ---------------------------------------------------------------------------
__global__ __launch_bounds__(256) void wconv_kernel(
    const float* __restrict__ W, __nv_bfloat16* __restrict__ Th,
    __nv_bfloat16* __restrict__ Tl, int K, int N)
{
    __shared__ float sm[32][33];
    int t = threadIdx.x;
    int tx = t & 31, ty = t >> 5;         // ty 0..7
    int k0 = blockIdx.x * 32, n0 = blockIdx.y * 32;
#pragma unroll
    for (int i = 0; i < 4; i++) {
        int r = ty + i * 8;
        sm[r][tx] = W[(size_t)(k0 + r) * N + n0 + tx];
    }
    __syncthreads();
#pragma unroll
    for (int i = 0; i < 4; i++) {
        int r = ty + i * 8;              // output row n0+r, col k0+tx
        float x = sm[tx][r];
        __nv_bfloat16 h, l;
        split_bf16(x, h, l);
        size_t o = (size_t)(n0 + r) * K + k0 + tx;
        Th[o] = h;
        Tl[o] = l;
    }
}

// ---------------------------------------------------------------------------
// Query fp32 -> bf16 hi/lo
// ---------------------------------------------------------------------------
__global__ __launch_bounds__(256) void qconv_kernel(const float* __restrict__ Q) {
    int idx = blockIdx.x * blockDim.x + threadIdx.x;
    float x = Q[idx];
    __nv_bfloat16 h, l;
    split_bf16(x, h, l);
    g_qry_h[idx] = h;
    g_qry_l[idx] = l;
}

// ---------------------------------------------------------------------------
// mma.sync bf16 split GEMM: C[4096,512] = A[4096,K] @ B^T (B stored [512,K])
// Tile 128x128, BK=32, 8 warps (2m x 4n), warp tile 64x32 (4x4 mma tiles).
// Products hh + hl + lh accumulated in fp32 registers.
// epi: 0 = +bias -> Cf ; 1 = silu(+bias) -> (Oh,Ol) bf16 ; 2 = +bias+resid -> Cf
// ---------------------------------------------------------------------------
#define PADK 40   // padded row stride in bf16 (20 words; 20 mod 32 pattern is conflict-free)

#define MMA16816(d, a, b) \
    asm volatile( \
        "mma.sync.aligned.m16n8k16.row.col.f32.bf16.bf16.f32 " \
        "{%0,%1,%2,%3}, {%4,%5,%6,%7}, {%8,%9}, {%0,%1,%2,%3};" \
        : "+f"((d)[0]), "+f"((d)[1]), "+f"((d)[2]), "+f"((d)[3]) \
        : "r"((a)[0]), "r"((a)[1]), "r"((a)[2]), "r"((a)[3]), \
          "r"((b)[0]), "r"((b)[1]))

__global__ __launch_bounds__(256) void gemm_mma(
    const __nv_bfloat16* __restrict__ Ah, const __nv_bfloat16* __restrict__ Al,
    const __nv_bfloat16* __restrict__ Bh, const __nv_bfloat16* __restrict__ Bl,
    const float* __restrict__ bias, const float* __restrict__ resid,
    float* __restrict__ Cf,
    __nv_bfloat16* __restrict__ Oh, __nv_bfloat16* __restrict__ Ol,
    int K, int epi)
{
    __shared__ __nv_bfloat16 sAh[128 * PADK];
    __shared__ __nv_bfloat16 sAl[128 * PADK];
    __shared__ __nv_bfloat16 sBh[128 * PADK];
    __shared__ __nv_bfloat16 sBl[128 * PADK];

    int t = threadIdx.x, lane = t & 31, wid = t >> 5;
    int wm = wid >> 2;        // 0..1 -> m offset wm*64
    int wn = wid & 3;         // 0..3 -> n offset wn*32
    int m0 = blockIdx.y * 128, n0 = blockIdx.x * 128;
    int gr = lane >> 2;       // 0..7
    int gc = lane & 3;        // 0..3

    float acc[4][4][4];
#pragma unroll
    for (int mi = 0; mi < 4; mi++)
#pragma unroll
        for (int ni = 0; ni < 4; ni++)
#pragma unroll
            for (int j = 0; j < 4; j++) acc[mi][ni][j] = 0.0f;

    for (int k0 = 0; k0 < K; k0 += 32) {
        // stage 4 tiles [128 x 32 bf16] into smem (padded stride PADK)
#pragma unroll
        for (int i = 0; i < 2; i++) {
            int idx = t + i * 256;        // uint4 slots: 0..511
            int row = idx >> 2;           // 0..127
            int slot = idx & 3;           // 4 x uint4 per 32-bf16 row
            size_t ga = (size_t)(m0 + row) * K + k0 + slot * 8;
            size_t gb = (size_t)(n0 + row) * K + k0 + slot * 8;
            *(uint4*)&sAh[row * PADK + slot * 8] = *(const uint4*)(Ah + ga);
            *(uint4*)&sAl[row * PADK + slot * 8] = *(const uint4*)(Al + ga);
            *(uint4*)&sBh[row * PADK + slot * 8] = *(const uint4*)(Bh + gb);
            *(uint4*)&sBl[row * PADK + slot * 8] = *(const uint4*)(Bl + gb);
        }
        __syncthreads();

#pragma unroll
        for (int ks = 0; ks < 2; ks++) {
            int kk = ks * 16;
            uint32_t ah[4][4], al[4][4], bh[4][2], bl[4][2];
#pragma unroll
            for (int mi = 0; mi < 4; mi++) {
                int r = wm * 64 + mi * 16 + gr;
                ah[mi][0] = *(const uint32_t*)&sAh[(r    ) * PADK + kk + gc * 2];
                ah[mi][1] = *(const uint32_t*)&sAh[(r + 8) * PADK + kk + gc * 2];
                ah[mi][2] = *(const uint32_t*)&sAh[(r    ) * PADK + kk + 8 + gc * 2];
                ah[mi][3] = *(const uint32_t*)&sAh[(r + 8) * PADK + kk + 8 + gc * 2];
                al[mi][0] = *(const uint32_t*)&sAl[(r    ) * PADK + kk + gc * 2];
                al[mi][1] = *(const uint32_t*)&sAl[(r + 8) * PADK + kk + gc * 2];
                al[mi][2] = *(const uint32_t*)&sAl[(r    ) * PADK + kk + 8 + gc * 2];
                al[mi][3] = *(const uint32_t*)&sAl[(r + 8) * PADK + kk + 8 + gc * 2];
            }
#pragma unroll
            for (int ni = 0; ni < 4; ni++) {
                int r = wn * 32 + ni * 8 + gr;
                bh[ni][0] = *(const uint32_t*)&sBh[r * PADK + kk + gc * 2];
                bh[ni][1] = *(const uint32_t*)&sBh[r * PADK + kk + 8 + gc * 2];
                bl[ni][0] = *(const uint32_t*)&sBl[r * PADK + kk + gc * 2];
                bl[ni][1] = *(const uint32_t*)&sBl[r * PADK + kk + 8 + gc * 2];
            }
#pragma unroll
            for (int mi = 0; mi < 4; mi++)
#pragma unroll
                for (int ni = 0; ni < 4; ni++) {
                    MMA16816(acc[mi][ni], ah[mi], bh[ni]);   // hi*hi
                    MMA16816(acc[mi][ni], ah[mi], bl[ni]);   // hi*lo
                    MMA16816(acc[mi][ni], al[mi], bh[ni]);   // lo*hi
                }
        }
        __syncthreads();
    }

    // Epilogue: fragment layout c0,c1 @ (row, col..col+1), c2,c3 @ (row+8, ...)
#pragma unroll
    for (int mi = 0; mi < 4; mi++) {
#pragma unroll
        for (int ni = 0; ni < 4; ni++) {
            int row0 = m0 + wm * 64 + mi * 16 + gr;
            int col  = n0 + wn * 32 + ni * 8 + gc * 2;
#pragma unroll
            for (int half = 0; half < 2; half++) {
                int row = row0 + half * 8;
                float v0 = acc[mi][ni][half * 2 + 0];
                float v1 = acc[mi][ni][half * 2 + 1];
                if (bias) { v0 += bias[col]; v1 += bias[col + 1]; }
                if (epi == 1) {
                    v0 = v0 / (1.0f + expf(-v0));
                    v1 = v1 / (1.0f + expf(-v1));
                    __nv_bfloat16 h0, l0, h1, l1;
                    split_bf16(v0, h0, l0);
                    split_bf16(v1, h1, l1);
                    size_t o = (size_t)row * CC + col;
                    Oh[o] = h0; Oh[o + 1] = h1;
                    Ol[o] = l0; Ol[o + 1] = l1;
                } else {
                    size_t o = (size_t)row * CC + col;
                    if (epi == 2) {
                        v0 += resid[o];
                        v1 += resid[o + 1];
                    }
                    float2 vv = make_float2(v0, v1);
                    *(float2*)(Cf + o) = vv;
                }
            }
        }
    }
}

// ---------------------------------------------------------------------------
// Fused attention: one block per (b,h).  Writes x as bf16 hi/lo.
// ---------------------------------------------------------------------------
__global__ __launch_bounds__(256) void attn_kernel() {
    int b = blockIdx.x;
    int h = blockIdx.y;

    __shared__ float ks[64][68];
    __shared__ float vs[64][68];
    __shared__ float qrow[64];
    __shared__ float s[64];

    int t = threadIdx.x;

#pragma unroll
    for (int i = 0; i < 4; i++) {
        int idx4 = t + i * 256;
        int m = idx4 >> 4;
        int d = (idx4 & 15) << 2;
        size_t off = (size_t)(b * 64 + m) * 512 + h * 64 + d;
        float4 kv = *(const float4*)(g_k + off);
        float4 vv = *(const float4*)(g_v + off);
        *(float4*)&ks[m][d] = kv;
        *(float4*)&vs[m][d] = vv;
    }
    __syncthreads();

    int m  = t >> 2;
    int dg = t & 3;
    const float* peb = g_pe + h * 64;

    for (int n = 0; n < 64; n++) {
        if (t < 16) {
            float4 qv = *(const float4*)(g_q + (size_t)(b * 64 + n) * 512 + h * 64 + t * 4);
            *(float4*)&qrow[t * 4] = qv;
        }
        __syncthreads();

        float p = 0.0f;
        const float* pep = peb + (size_t)(n * 64 + m) * 512 + dg * 16;
#pragma unroll
        for (int i = 0; i < 4; i++) {
            float4 pe4 = *(const float4*)(pep + i * 4);
            int d = dg * 16 + i * 4;
            p = fmaf(qrow[d + 0] * ks[m][d + 0], pe4.x, p);
            p = fmaf(qrow[d + 1] * ks[m][d + 1], pe4.y, p);
            p = fmaf(qrow[d + 2] * ks[m][d + 2], pe4.z, p);
            p = fmaf(qrow[d + 3] * ks[m][d + 3], pe4.w, p);
        }
        p += __shfl_xor_sync(0xffffffffu, p, 1);
        p += __shfl_xor_sync(0xffffffffu, p, 2);
        if (dg == 0) s[m] = p * 0.125f;
        __syncthreads();

        if (t < 32) {
            float a  = s[t];
            float c2 = s[t + 32];
            float mx = fmaxf(a, c2);
#pragma unroll
            for (int off = 16; off > 0; off >>= 1)
                mx = fmaxf(mx, __shfl_xor_sync(0xffffffffu, mx, off));
            float e1 = __expf(a - mx), e2 = __expf(c2 - mx);
            float sm = e1 + e2;
#pragma unroll
            for (int off = 16; off > 0; off >>= 1)
                sm += __shfl_xor_sync(0xffffffffu, sm, off);
            float inv = 1.0f / sm;
            s[t]      = e1 * inv;
            s[t + 32] = e2 * inv;
        }
        __syncthreads();

        if (t < 64) {
            float xv = 0.0f;
#pragma unroll
            for (int mm = 0; mm < 64; mm++)
                xv = fmaf(s[mm], vs[mm][t], xv);
            __nv_bfloat16 hh, ll;
            split_bf16(xv, hh, ll);
            size_t o = (size_t)(b * 64 + n) * 512 + h * 64 + t;
            g_x_h[o] = hh;
            g_x_l[o] = ll;
        }
        __syncthreads();
    }
}

// ---------------------------------------------------------------------------
// Launch
// ---------------------------------------------------------------------------
extern "C" void kernel_launch(void* const* d_in, const int* in_sizes, int n_in,
                              void* d_out, int out_size)
{
    const float* query = (const float*)d_in[0];
    const float* qpos  = (const float*)d_in[1];
    const float* Wq    = (const float*)d_in[2];
    const float* bq    = (const float*)d_in[3];
    const float* Wk    = (const float*)d_in[4];
    const float* Wv    = (const float*)d_in[5];
    const float* bv    = (const float*)d_in[6];
    const float* Wo    = (const float*)d_in[7];
    const float* bo    = (const float*)d_in[8];
    const float* W1    = (const float*)d_in[9];
    const float* b1    = (const float*)d_in[10];
    const float* W2    = (const float*)d_in[11];
    const float* b2    = (const float*)d_in[12];
    float* out = (float*)d_out;

    void *p_pe, *p_q, *p_k, *p_v;
    void *p_embh, *p_embl, *p_hidh, *p_hidl, *p_qryh, *p_qryl, *p_xh, *p_xl;
    void *p_wh, *p_wl;
    cudaGetSymbolAddress(&p_pe,  g_pe);
    cudaGetSymbolAddress(&p_q,   g_q);
    cudaGetSymbolAddress(&p_k,   g_k);
    cudaGetSymbolAddress(&p_v,   g_v);
    cudaGetSymbolAddress(&p_embh, g_emb_h);
    cudaGetSymbolAddress(&p_embl, g_emb_l);
    cudaGetSymbolAddress(&p_hidh, g_hid_h);
    cudaGetSymbolAddress(&p_hidl, g_hid_l);
    cudaGetSymbolAddress(&p_qryh, g_qry_h);
    cudaGetSymbolAddress(&p_qryl, g_qry_l);
    cudaGetSymbolAddress(&p_xh,   g_x_h);
    cudaGetSymbolAddress(&p_xl,   g_x_l);
    cudaGetSymbolAddress(&p_wh,   g_w_h);
    cudaGetSymbolAddress(&p_wl,   g_w_l);

    __nv_bfloat16* wh = (__nv_bfloat16*)p_wh;
    __nv_bfloat16* wl = (__nv_bfloat16*)p_wl;
    const int WSLOT = CC * CC;
    // slots: 0=W1t(512x256), 1=W2t, 2=Wqt, 3=Wkt, 4=Wvt, 5=Wot

    // 1) embedding -> bf16 hi/lo
    embed_kernel<<<4096, 256>>>(qpos);

    // 2) weight transpose + split
    wconv_kernel<<<dim3(8, 16),  256>>>(W1, wh + 0 * WSLOT, wl + 0 * WSLOT, FREQE, CC);
    wconv_kernel<<<dim3(16, 16), 256>>>(W2, wh + 1 * WSLOT, wl + 1 * WSLOT, CC, CC);
    wconv_kernel<<<dim3(16, 16), 256>>>(Wq, wh + 2 * WSLOT, wl + 2 * WSLOT, CC, CC);
    wconv_kernel<<<dim3(16, 16), 256>>>(Wk, wh + 3 * WSLOT, wl + 3 * WSLOT, CC, CC);
    wconv_kernel<<<dim3(16, 16), 256>>>(Wv, wh + 4 * WSLOT, wl + 4 * WSLOT, CC, CC);
    wconv_kernel<<<dim3(16, 16), 256>>>(Wo, wh + 5 * WSLOT, wl + 5 * WSLOT, CC, CC);

    // 3) query -> bf16 hi/lo
    qconv_kernel<<<ROWS * CC / 256, 256>>>(query);

    dim3 gg(4, 32);   // N/128=4, M/128=32

    // 4) pe MLP
    gemm_mma<<<gg, 256>>>(
        (const __nv_bfloat16*)p_embh, (const __nv_bfloat16*)p_embl,
        wh + 0 * WSLOT, wl + 0 * WSLOT, b1, nullptr,
        nullptr, (__nv_bfloat16*)p_hidh, (__nv_bfloat16*)p_hidl, FREQE, 1);
    gemm_mma<<<gg, 256>>>(
        (const __nv_bfloat16*)p_hidh, (const __nv_bfloat16*)p_hidl,
        wh + 1 * WSLOT, wl + 1 * WSLOT, b2, nullptr,
        (float*)p_pe, nullptr, nullptr, CC, 0);

    // 5) q / k / v projections
    gemm_mma<<<gg, 256>>>(
        (const __nv_bfloat16*)p_qryh, (const __nv_bfloat16*)p_qryl,
        wh + 2 * WSLOT, wl + 2 * WSLOT, bq, nullptr,
        (float*)p_q, nullptr, nullptr, CC, 0);
    gemm_mma<<<gg, 256>>>(
        (const __nv_bfloat16*)p_qryh, (const __nv_bfloat16*)p_qryl,
        wh + 3 * WSLOT, wl + 3 * WSLOT, nullptr, nullptr,
        (float*)p_k, nullptr, nullptr, CC, 0);
    gemm_mma<<<gg, 256>>>(
        (const __nv_bfloat16*)p_qryh, (const __nv_bfloat16*)p_qryl,
        wh + 4 * WSLOT, wl + 4 * WSLOT, bv, nullptr,
        (float*)p_v, nullptr, nullptr, CC, 0);

    // 6) fused pe-modulated attention -> x hi/lo
    attn_kernel<<<dim3(BB, HH), 256>>>();

    // 7) output projection + residual
    gemm_mma<<<gg, 256>>>(
        (const __nv_bfloat16*)p_xh, (const __nv_bfloat16*)p_xl,
        wh + 5 * WSLOT, wl + 5 * WSLOT, bo, query,
        out, nullptr, nullptr, CC, 2);
}

// round 4
// speedup vs baseline: 1.8828x; 1.0709x over previous
#include <cuda_runtime.h>
#include <cuda_bf16.h>
#include <math.h>
#include <stdint.h>

// Problem constants
#define BB    64
#define CC    512
#define HH    8
#define HD    64
#define FREQE 256
#define ROWS  4096   // B*N == N*M

// ---------------------------------------------------------------------------
// Scratch (device globals; no allocation allowed)
// ---------------------------------------------------------------------------
__device__ float g_pe[ROWS * CC];
__device__ float g_q [ROWS * CC];
__device__ float g_k [ROWS * CC];
__device__ float g_v [ROWS * CC];

__device__ __nv_bfloat16 g_emb_h[ROWS * FREQE];
__device__ __nv_bfloat16 g_emb_l[ROWS * FREQE];
__device__ __nv_bfloat16 g_hid_h[ROWS * CC];
__device__ __nv_bfloat16 g_hid_l[ROWS * CC];
__device__ __nv_bfloat16 g_qry_h[ROWS * CC];
__device__ __nv_bfloat16 g_qry_l[ROWS * CC];
__device__ __nv_bfloat16 g_x_h [ROWS * CC];
__device__ __nv_bfloat16 g_x_l [ROWS * CC];
__device__ __nv_bfloat16 g_w_h [6 * CC * CC];   // transposed weights [N,K], hi
__device__ __nv_bfloat16 g_w_l [6 * CC * CC];   // transposed weights [N,K], lo

__device__ __forceinline__ void split_bf16(float x, __nv_bfloat16& h, __nv_bfloat16& l) {
    h = __float2bfloat16(x);
    l = __float2bfloat16(x - __bfloat162float(h));
}

__device__ __forceinline__ uint32_t smem_u32(const void* p) {
    uint32_t a;
    asm("{ .reg .u64 t; cvta.to.shared.u64 t, %1; cvt.u32.u64 %0, t; }"
        : "=r"(a) : "l"(p));
    return a;
}

__device__ __forceinline__ void cp16(uint32_t dst, const void* src) {
    asm volatile("cp.async.cg.shared.global [%0], [%1], 16;" :: "r"(dst), "l"(src));
}
#define CP_COMMIT() asm volatile("cp.async.commit_group;" ::: "memory")
#define CP_WAIT(n)  asm volatile("cp.async.wait_group %0;" :: "n"(n) : "memory")

__device__ __forceinline__ void ldsm4(uint32_t addr, uint32_t& r0, uint32_t& r1,
                                      uint32_t& r2, uint32_t& r3) {
    asm volatile("ldmatrix.sync.aligned.m8n8.x4.shared.b16 {%0,%1,%2,%3}, [%4];"
        : "=r"(r0), "=r"(r1), "=r"(r2), "=r"(r3) : "r"(addr));
}

// ---------------------------------------------------------------------------
// Sinusoidal embedding -> bf16 hi/lo
// ---------------------------------------------------------------------------
__global__ __launch_bounds__(256) void embed_kernel(const float* __restrict__ qpos) {
    int idx = blockIdx.x * blockDim.x + threadIdx.x;   // 0 .. 4096*256-1
    int p = idx >> 8;
    int j = idx & 255;
    float t = qpos[p];
    int jj = j & 127;
    float f = expf(-9.210340371976184f * (float)jj * (1.0f / 128.0f));
    float a = t * f;
    float v = (j < 128) ? cosf(a) : sinf(a);
    __nv_bfloat16 h, l;
    split_bf16(v, h, l);
    g_emb_h[idx] = h;
    g_emb_l[idx] = l;
}

// ---------------------------------------------------------------------------
// Weight transpose + hi/lo split: W[K,N] fp32 -> Wt[N,K] bf16 (hi,lo)
// ---------------------------------------------------------------------------
__global__ __launch_bounds__(256) void wconv_kernel(
    const float* __restrict__ W, __nv_bfloat16* __restrict__ Th,
    __nv_bfloat16* __restrict__ Tl, int K, int N)
{
    __shared__ float sm[32][33];
    int t = threadIdx.x;
    int tx = t & 31, ty = t >> 5;
    int k0 = blockIdx.x * 32, n0 = blockIdx.y * 32;
#pragma unroll
    for (int i = 0; i < 4; i++) {
        int r = ty + i * 8;
        sm[r][tx] = W[(size_t)(k0 + r) * N + n0 + tx];
    }
    __syncthreads();
#pragma unroll
    for (int i = 0; i < 4; i++) {
        int r = ty + i * 8;
        float x = sm[tx][r];
        __nv_bfloat16 h, l;
        split_bf16(x, h, l);
        size_t o = (size_t)(n0 + r) * K + k0 + tx;
        Th[o] = h;
        Tl[o] = l;
    }
}

// ---------------------------------------------------------------------------
// Query fp32 -> bf16 hi/lo
// ---------------------------------------------------------------------------
__global__ __launch_bounds__(256) void qconv_kernel(const float* __restrict__ Q) {
    int idx = blockIdx.x * blockDim.x + threadIdx.x;
    float x = Q[idx];
    __nv_bfloat16 h, l;
    split_bf16(x, h, l);
    g_qry_h[idx] = h;
    g_qry_l[idx] = l;
}

// ---------------------------------------------------------------------------
// mma.sync bf16 split GEMM, cp.async double-buffered + ldmatrix fragments.
// C[4096,512] = A[4096,K] @ B^T (B stored [512,K]).
// Tile 128x128, BK=32, 8 warps (2m x 4n), warp tile 64x32.
// Products hh + hl + lh accumulated in fp32 registers.
// epi: 0 = +bias -> Cf ; 1 = silu(+bias) -> (Oh,Ol) bf16 ; 2 = +bias+resid -> Cf
// ---------------------------------------------------------------------------
#define PADB 80                       // bytes per smem tile row (40 bf16)
#define TILEB (128 * PADB)            // 10240 bytes per tile
#define GSMEM (8 * TILEB)             // 4 tiles x 2 stages = 81920 bytes

#define MMA16816(d, a, b) \
    asm volatile( \
        "mma.sync.aligned.m16n8k16.row.col.f32.bf16.bf16.f32 " \
        "{%0,%1,%2,%3}, {%4,%5,%6,%7}, {%8,%9}, {%0,%1,%2,%3};" \
        : "+f"((d)[0]), "+f"((d)[1]), "+f"((d)[2]), "+f"((d)[3]) \
        : "r"((a)[0]), "r"((a)[1]), "r"((a)[2]), "r"((a)[3]), \
          "r"((b)[0]), "r"((b)[1]))

__global__ __launch_bounds__(256) void gemm_mma(
    const __nv_bfloat16* __restrict__ Ah, const __nv_bfloat16* __restrict__ Al,
    const __nv_bfloat16* __restrict__ Bh, const __nv_bfloat16* __restrict__ Bl,
    const float* __restrict__ bias, const float* __restrict__ resid,
    float* __restrict__ Cf,
    __nv_bfloat16* __restrict__ Oh, __nv_bfloat16* __restrict__ Ol,
    int K, int epi)
{
    extern __shared__ char smem[];
    uint32_t sbase = smem_u32(smem);

    int t = threadIdx.x, lane = t & 31, wid = t >> 5;
    int wm = wid >> 2;        // 0..1 -> m offset wm*64
    int wn = wid & 3;         // 0..3 -> n offset wn*32
    int m0 = blockIdx.y * 128, n0 = blockIdx.x * 128;

    float acc[4][4][4];
#pragma unroll
    for (int mi = 0; mi < 4; mi++)
#pragma unroll
        for (int ni = 0; ni < 4; ni++)
#pragma unroll
            for (int j = 0; j < 4; j++) acc[mi][ni][j] = 0.0f;

    // cp.async staging indices (per thread): 2 x (row, 16B-chunk) per tile
    int ldrow0 = t >> 2,        ldc0 = t & 3;
    int ldrow1 = (t + 256) >> 2, ldc1 = (t + 256) & 3;

    int nch = K >> 5;

    // ---- stage loader (macro-ish lambda) ----
    auto load_chunk = [&](int ch, int buf) {
        int k0 = ch << 5;
        {
            uint32_t off = (uint32_t)(ldrow0 * PADB + ldc0 * 16);
            const __nv_bfloat16* pa = Ah + (size_t)(m0 + ldrow0) * K + k0 + ldc0 * 8;
            const __nv_bfloat16* pl = Al + (size_t)(m0 + ldrow0) * K + k0 + ldc0 * 8;
            const __nv_bfloat16* pb = Bh + (size_t)(n0 + ldrow0) * K + k0 + ldc0 * 8;
            const __nv_bfloat16* pc = Bl + (size_t)(n0 + ldrow0) * K + k0 + ldc0 * 8;
            cp16(sbase + (0 * 2 + buf) * TILEB + off, pa);
            cp16(sbase + (1 * 2 + buf) * TILEB + off, pl);
            cp16(sbase + (2 * 2 + buf) * TILEB + off, pb);
            cp16(sbase + (3 * 2 + buf) * TILEB + off, pc);
        }
        {
            uint32_t off = (uint32_t)(ldrow1 * PADB + ldc1 * 16);
            const __nv_bfloat16* pa = Ah + (size_t)(m0 + ldrow1) * K + k0 + ldc1 * 8;
            const __nv_bfloat16* pl = Al + (size_t)(m0 + ldrow1) * K + k0 + ldc1 * 8;
            const __nv_bfloat16* pb = Bh + (size_t)(n0 + ldrow1) * K + k0 + ldc1 * 8;
            const __nv_bfloat16* pc = Bl + (size_t)(n0 + ldrow1) * K + k0 + ldc1 * 8;
            cp16(sbase + (0 * 2 + buf) * TILEB + off, pa);
            cp16(sbase + (1 * 2 + buf) * TILEB + off, pl);
            cp16(sbase + (2 * 2 + buf) * TILEB + off, pb);
            cp16(sbase + (3 * 2 + buf) * TILEB + off, pc);
        }
        CP_COMMIT();
    };

    // ldmatrix lane addressing
    int g  = lane >> 3, lr = lane & 7;
    uint32_t arow = (uint32_t)((wm * 64 + (g & 1) * 8 + lr) * PADB + ((g >> 1) * 16));
    uint32_t brow = (uint32_t)((wn * 32 + (g >> 1) * 8 + lr) * PADB + ((g & 1) * 16));

    // prologue: stage chunks 0 and 1
    load_chunk(0, 0);
    load_chunk(1, 1);

    for (int ch = 0; ch < nch; ch++) {
        if (ch + 1 < nch) { CP_WAIT(1); } else { CP_WAIT(0); }
        __syncthreads();

        int buf = ch & 1;
        uint32_t aAh = sbase + (0 * 2 + buf) * TILEB;
        uint32_t aAl = sbase + (1 * 2 + buf) * TILEB;
        uint32_t aBh = sbase + (2 * 2 + buf) * TILEB;
        uint32_t aBl = sbase + (3 * 2 + buf) * TILEB;

#pragma unroll
        for (int ks = 0; ks < 2; ks++) {
            uint32_t koff = (uint32_t)(ks * 32);
            uint32_t ah[4][4], al[4][4], bh[4][2], bl[4][2];
#pragma unroll
            for (int mi = 0; mi < 4; mi++) {
                ldsm4(aAh + arow + mi * (16 * PADB) + koff,
                      ah[mi][0], ah[mi][1], ah[mi][2], ah[mi][3]);
                ldsm4(aAl + arow + mi * (16 * PADB) + koff,
                      al[mi][0], al[mi][1], al[mi][2], al[mi][3]);
            }
#pragma unroll
            for (int np = 0; np < 2; np++) {
                ldsm4(aBh + brow + np * (16 * PADB) + koff,
                      bh[2*np][0], bh[2*np][1], bh[2*np+1][0], bh[2*np+1][1]);
                ldsm4(aBl + brow + np * (16 * PADB) + koff,
                      bl[2*np][0], bl[2*np][1], bl[2*np+1][0], bl[2*np+1][1]);
            }
#pragma unroll
            for (int mi = 0; mi < 4; mi++)
#pragma unroll
                for (int ni = 0; ni < 4; ni++) {
                    MMA16816(acc[mi][ni], ah[mi], bh[ni]);   // hi*hi
                    MMA16816(acc[mi][ni], ah[mi], bl[ni]);   // hi*lo
                    MMA16816(acc[mi][ni], al[mi], bh[ni]);   // lo*hi
                }
        }
        __syncthreads();
        if (ch + 2 < nch) load_chunk(ch + 2, buf);
    }

    // Epilogue: frag c0,c1 @ (row, col..col+1), c2,c3 @ (row+8, ...)
    int gr = lane >> 2, gc = lane & 3;
#pragma unroll
    for (int mi = 0; mi < 4; mi++) {
#pragma unroll
        for (int ni = 0; ni < 4; ni++) {
            int row0 = m0 + wm * 64 + mi * 16 + gr;
            int col  = n0 + wn * 32 + ni * 8 + gc * 2;
#pragma unroll
            for (int half = 0; half < 2; half++) {
                int row = row0 + half * 8;
                float v0 = acc[mi][ni][half * 2 + 0];
                float v1 = acc[mi][ni][half * 2 + 1];
                if (bias) { v0 += bias[col]; v1 += bias[col + 1]; }
                if (epi == 1) {
                    v0 = v0 / (1.0f + expf(-v0));
                    v1 = v1 / (1.0f + expf(-v1));
                    __nv_bfloat16 h0, l0, h1, l1;
                    split_bf16(v0, h0, l0);
                    split_bf16(v1, h1, l1);
                    size_t o = (size_t)row * CC + col;
                    Oh[o] = h0; Oh[o + 1] = h1;
                    Ol[o] = l0; Ol[o + 1] = l1;
                } else {
                    size_t o = (size_t)row * CC + col;
                    if (epi == 2) {
                        v0 += resid[o];
                        v1 += resid[o + 1];
                    }
                    *(float2*)(Cf + o) = make_float2(v0, v1);
                }
            }
        }
    }
}

// ---------------------------------------------------------------------------
// Fused attention, 4 batches per block: grid (16 bgroups, 8 heads).
// K rows and V columns register-resident; pe streamed from L2 (shared by 4 b).
// ---------------------------------------------------------------------------
#define ATTN_SMEM (4 * 64 * 68 * 4)   // 69632-byte staging buffer

__global__ __launch_bounds__(256, 1) void attn_kernel() {
    extern __shared__ float kv[];      // staging: [4][64][68]
    __shared__ float qrow[4][64];
    __shared__ float s[4][64];

    int h   = blockIdx.y;
    int bg0 = blockIdx.x * 4;
    int t   = threadIdx.x;
    int bh  = t >> 6;      // 0..3 local batch
    int i   = t & 63;      // m for scores, d for AV

    float kreg[64], vreg[64];

    // stage K (coalesced), pull row i into registers
#pragma unroll
    for (int it = 0; it < 16; it++) {
        int slot = t + it * 256;           // 0..4095 float4 slots
        int b  = slot >> 10;
        int m  = (slot >> 4) & 63;
        int d4 = slot & 15;
        float4 x = *(const float4*)(g_k + ((size_t)((bg0 + b) * 64 + m)) * 512 + h * 64 + d4 * 4);
        *(float4*)&kv[(b * 64 + m) * 68 + d4 * 4] = x;
    }
    __syncthreads();
#pragma unroll
    for (int d = 0; d < 64; d++) kreg[d] = kv[(bh * 64 + i) * 68 + d];
    __syncthreads();

    // stage V, pull column i into registers
#pragma unroll
    for (int it = 0; it < 16; it++) {
        int slot = t + it * 256;
        int b  = slot >> 10;
        int m  = (slot >> 4) & 63;
        int d4 = slot & 15;
        float4 x = *(const float4*)(g_v + ((size_t)((bg0 + b) * 64 + m)) * 512 + h * 64 + d4 * 4);
        *(float4*)&kv[(b * 64 + m) * 68 + d4 * 4] = x;
    }
    __syncthreads();
#pragma unroll
    for (int m = 0; m < 64; m++) vreg[m] = kv[(bh * 64 + m) * 68 + i];
    __syncthreads();

    for (int n = 0; n < 64; n++) {
        if (t < 64) {
            int b = t >> 4, w = t & 15;
            float4 qv = *(const float4*)(g_q + ((size_t)((bg0 + b) * 64 + n)) * 512 + h * 64 + w * 4);
            *(float4*)&qrow[b][w * 4] = qv;
        }
        __syncthreads();

        // scores: thread (bh, m=i)
        const float* pep = g_pe + ((size_t)(n * 64 + i)) * 512 + h * 64;
        float p = 0.0f;
#pragma unroll
        for (int d4 = 0; d4 < 16; d4++) {
            float4 pe4 = *(const float4*)(pep + d4 * 4);
            int d = d4 * 4;
            p = fmaf(qrow[bh][d + 0] * kreg[d + 0], pe4.x, p);
            p = fmaf(qrow[bh][d + 1] * kreg[d + 1], pe4.y, p);
            p = fmaf(qrow[bh][d + 2] * kreg[d + 2], pe4.z, p);
            p = fmaf(qrow[bh][d + 3] * kreg[d + 3], pe4.w, p);
        }
        s[bh][i] = p * 0.125f;
        __syncthreads();

        // softmax: warp w handles batch w
        if (t < 128) {
            int w = t >> 5, lane = t & 31;
            float a  = s[w][lane];
            float c2 = s[w][lane + 32];
            float mx = fmaxf(a, c2);
#pragma unroll
            for (int off = 16; off > 0; off >>= 1)
                mx = fmaxf(mx, __shfl_xor_sync(0xffffffffu, mx, off));
            float e1 = __expf(a - mx), e2 = __expf(c2 - mx);
            float sm = e1 + e2;
#pragma unroll
            for (int off = 16; off > 0; off >>= 1)
                sm += __shfl_xor_sync(0xffffffffu, sm, off);
            float inv = 1.0f / sm;
            s[w][lane]      = e1 * inv;
            s[w][lane + 32] = e2 * inv;
        }
        __syncthreads();

        // AV: thread (bh, d=i)
        float xv = 0.0f;
#pragma unroll
        for (int m = 0; m < 64; m++)
            xv = fmaf(s[bh][m], vreg[m], xv);
        __nv_bfloat16 hh, ll;
        split_bf16(xv, hh, ll);
        size_t o = ((size_t)((bg0 + bh) * 64 + n)) * 512 + h * 64 + i;
        g_x_h[o] = hh;
        g_x_l[o] = ll;
        __syncthreads();
    }
}

// ---------------------------------------------------------------------------
// Launch
// ---------------------------------------------------------------------------
extern "C" void kernel_launch(void* const* d_in, const int* in_sizes, int n_in,
                              void* d_out, int out_size)
{
    const float* query = (const float*)d_in[0];
    const float* qpos  = (const float*)d_in[1];
    const float* Wq    = (const float*)d_in[2];
    const float* bq    = (const float*)d_in[3];
    const float* Wk    = (const float*)d_in[4];
    const float* Wv    = (const float*)d_in[5];
    const float* bv    = (const float*)d_in[6];
    const float* Wo    = (const float*)d_in[7];
    const float* bo    = (const float*)d_in[8];
    const float* W1    = (const float*)d_in[9];
    const float* b1    = (const float*)d_in[10];
    const float* W2    = (const float*)d_in[11];
    const float* b2    = (const float*)d_in[12];
    float* out = (float*)d_out;

    cudaFuncSetAttribute(gemm_mma, cudaFuncAttributeMaxDynamicSharedMemorySize, GSMEM);
    cudaFuncSetAttribute(attn_kernel, cudaFuncAttributeMaxDynamicSharedMemorySize, ATTN_SMEM);

    void *p_pe, *p_q, *p_k, *p_v;
    void *p_embh, *p_embl, *p_hidh, *p_hidl, *p_qryh, *p_qryl, *p_xh, *p_xl;
    void *p_wh, *p_wl;
    cudaGetSymbolAddress(&p_pe,  g_pe);
    cudaGetSymbolAddress(&p_q,   g_q);
    cudaGetSymbolAddress(&p_k,   g_k);
    cudaGetSymbolAddress(&p_v,   g_v);
    cudaGetSymbolAddress(&p_embh, g_emb_h);
    cudaGetSymbolAddress(&p_embl, g_emb_l);
    cudaGetSymbolAddress(&p_hidh, g_hid_h);
    cudaGetSymbolAddress(&p_hidl, g_hid_l);
    cudaGetSymbolAddress(&p_qryh, g_qry_h);
    cudaGetSymbolAddress(&p_qryl, g_qry_l);
    cudaGetSymbolAddress(&p_xh,   g_x_h);
    cudaGetSymbolAddress(&p_xl,   g_x_l);
    cudaGetSymbolAddress(&p_wh,   g_w_h);
    cudaGetSymbolAddress(&p_wl,   g_w_l);

    __nv_bfloat16* wh = (__nv_bfloat16*)p_wh;
    __nv_bfloat16* wl = (__nv_bfloat16*)p_wl;
    const int WSLOT = CC * CC;
    // slots: 0=W1t(512x256), 1=W2t, 2=Wqt, 3=Wkt, 4=Wvt, 5=Wot

    // 1) embedding -> bf16 hi/lo
    embed_kernel<<<4096, 256>>>(qpos);

    // 2) weight transpose + split
    wconv_kernel<<<dim3(8, 16),  256>>>(W1, wh + 0 * WSLOT, wl + 0 * WSLOT, FREQE, CC);
    wconv_kernel<<<dim3(16, 16), 256>>>(W2, wh + 1 * WSLOT, wl + 1 * WSLOT, CC, CC);
    wconv_kernel<<<dim3(16, 16), 256>>>(Wq, wh + 2 * WSLOT, wl + 2 * WSLOT, CC, CC);
    wconv_kernel<<<dim3(16, 16), 256>>>(Wk, wh + 3 * WSLOT, wl + 3 * WSLOT, CC, CC);
    wconv_kernel<<<dim3(16, 16), 256>>>(Wv, wh + 4 * WSLOT, wl + 4 * WSLOT, CC, CC);
    wconv_kernel<<<dim3(16, 16), 256>>>(Wo, wh + 5 * WSLOT, wl + 5 * WSLOT, CC, CC);

    // 3) query -> bf16 hi/lo
    qconv_kernel<<<ROWS * CC / 256, 256>>>(query);

    dim3 gg(4, 32);   // N/128=4, M/128=32

    // 4) pe MLP
    gemm_mma<<<gg, 256, GSMEM>>>(
        (const __nv_bfloat16*)p_embh, (const __nv_bfloat16*)p_embl,
        wh + 0 * WSLOT, wl + 0 * WSLOT, b1, nullptr,
        nullptr, (__nv_bfloat16*)p_hidh, (__nv_bfloat16*)p_hidl, FREQE, 1);
    gemm_mma<<<gg, 256, GSMEM>>>(
        (const __nv_bfloat16*)p_hidh, (const __nv_bfloat16*)p_hidl,
        wh + 1 * WSLOT, wl + 1 * WSLOT, b2, nullptr,
        (float*)p_pe, nullptr, nullptr, CC, 0);

    // 5) q / k / v projections
    gemm_mma<<<gg, 256, GSMEM>>>(
        (const __nv_bfloat16*)p_qryh, (const __nv_bfloat16*)p_qryl,
        wh + 2 * WSLOT, wl + 2 * WSLOT, bq, nullptr,
        (float*)p_q, nullptr, nullptr, CC, 0);
    gemm_mma<<<gg, 256, GSMEM>>>(
        (const __nv_bfloat16*)p_qryh, (const __nv_bfloat16*)p_qryl,
        wh + 3 * WSLOT, wl + 3 * WSLOT, nullptr, nullptr,
        (float*)p_k, nullptr, nullptr, CC, 0);
    gemm_mma<<<gg, 256, GSMEM>>>(
        (const __nv_bfloat16*)p_qryh, (const __nv_bfloat16*)p_qryl,
        wh + 4 * WSLOT, wl + 4 * WSLOT, bv, nullptr,
        (float*)p_v, nullptr, nullptr, CC, 0);

    // 6) fused pe-modulated attention -> x hi/lo
    attn_kernel<<<dim3(16, HH), 256, ATTN_SMEM>>>();

    // 7) output projection + residual
    gemm_mma<<<gg, 256, GSMEM>>>(
        (const __nv_bfloat16*)p_xh, (const __nv_bfloat16*)p_xl,
        wh + 5 * WSLOT, wl + 5 * WSLOT, bo, query,
        out, nullptr, nullptr, CC, 2);
}

// round 5
// speedup vs baseline: 1.9088x; 1.0138x over previous
#include <cuda_runtime.h>
#include <cuda_bf16.h>
#include <math.h>
#include <stdint.h>

// Problem constants
#define BB    64
#define CC    512
#define HH    8
#define HD    64
#define FREQE 256
#define ROWS  4096   // B*N == N*M

// ---------------------------------------------------------------------------
// Scratch (device globals; no allocation allowed)
// ---------------------------------------------------------------------------
__device__ float g_pe[ROWS * CC];
__device__ float g_q [ROWS * CC];
__device__ float g_k [ROWS * CC];
__device__ float g_v [ROWS * CC];
__device__ float g_bqkv[3 * CC];

__device__ __nv_bfloat16 g_emb_h[ROWS * FREQE];
__device__ __nv_bfloat16 g_emb_l[ROWS * FREQE];
__device__ __nv_bfloat16 g_hid_h[ROWS * CC];
__device__ __nv_bfloat16 g_hid_l[ROWS * CC];
__device__ __nv_bfloat16 g_qry_h[ROWS * CC];
__device__ __nv_bfloat16 g_qry_l[ROWS * CC];
__device__ __nv_bfloat16 g_x_h [ROWS * CC];
__device__ __nv_bfloat16 g_x_l [ROWS * CC];
__device__ __nv_bfloat16 g_w_h [6 * CC * CC];   // transposed weights [N,K], hi
__device__ __nv_bfloat16 g_w_l [6 * CC * CC];   // transposed weights [N,K], lo

__device__ __forceinline__ void split_bf16(float x, __nv_bfloat16& h, __nv_bfloat16& l) {
    h = __float2bfloat16(x);
    l = __float2bfloat16(x - __bfloat162float(h));
}

__device__ __forceinline__ uint32_t smem_u32(const void* p) {
    uint32_t a;
    asm("{ .reg .u64 t; cvta.to.shared.u64 t, %1; cvt.u32.u64 %0, t; }"
        : "=r"(a) : "l"(p));
    return a;
}

__device__ __forceinline__ void cp16(uint32_t dst, const void* src) {
    asm volatile("cp.async.cg.shared.global [%0], [%1], 16;" :: "r"(dst), "l"(src));
}
#define CP_COMMIT() asm volatile("cp.async.commit_group;" ::: "memory")
#define CP_WAIT(n)  asm volatile("cp.async.wait_group %0;" :: "n"(n) : "memory")

__device__ __forceinline__ void ldsm4(uint32_t addr, uint32_t& r0, uint32_t& r1,
                                      uint32_t& r2, uint32_t& r3) {
    asm volatile("ldmatrix.sync.aligned.m8n8.x4.shared.b16 {%0,%1,%2,%3}, [%4];"
        : "=r"(r0), "=r"(r1), "=r"(r2), "=r"(r3) : "r"(addr));
}

// ---------------------------------------------------------------------------
// Sinusoidal embedding -> bf16 hi/lo
// ---------------------------------------------------------------------------
__global__ __launch_bounds__(256) void embed_kernel(const float* __restrict__ qpos) {
    int idx = blockIdx.x * blockDim.x + threadIdx.x;   // 0 .. 4096*256-1
    int p = idx >> 8;
    int j = idx & 255;
    float t = qpos[p];
    int jj = j & 127;
    float f = expf(-9.210340371976184f * (float)jj * (1.0f / 128.0f));
    float a = t * f;
    float v = (j < 128) ? cosf(a) : sinf(a);
    __nv_bfloat16 h, l;
    split_bf16(v, h, l);
    g_emb_h[idx] = h;
    g_emb_l[idx] = l;
}

// ---------------------------------------------------------------------------
// All 6 weight transposes + hi/lo split in ONE launch.
// slot z: 0=W1(K=256) 1=W2 2=Wq 3=Wk 4=Wv 5=Wo (K=512)
// ---------------------------------------------------------------------------
__global__ __launch_bounds__(256) void wconv_all(
    const float* __restrict__ W1, const float* __restrict__ W2,
    const float* __restrict__ Wq, const float* __restrict__ Wk,
    const float* __restrict__ Wv, const float* __restrict__ Wo)
{
    __shared__ float sm[32][33];
    int slot = blockIdx.z;
    int K = (slot == 0) ? FREQE : CC;
    int k0 = blockIdx.x * 32, n0 = blockIdx.y * 32;
    if (k0 >= K) return;

    const float* W = (slot == 0) ? W1 : (slot == 1) ? W2 : (slot == 2) ? Wq
                   : (slot == 3) ? Wk : (slot == 4) ? Wv : Wo;
    __nv_bfloat16* Th = g_w_h + (size_t)slot * CC * CC;
    __nv_bfloat16* Tl = g_w_l + (size_t)slot * CC * CC;

    int t = threadIdx.x;
    int tx = t & 31, ty = t >> 5;
#pragma unroll
    for (int i = 0; i < 4; i++) {
        int r = ty + i * 8;
        sm[r][tx] = W[(size_t)(k0 + r) * CC + n0 + tx];
    }
    __syncthreads();
#pragma unroll
    for (int i = 0; i < 4; i++) {
        int r = ty + i * 8;
        float x = sm[tx][r];
        __nv_bfloat16 h, l;
        split_bf16(x, h, l);
        size_t o = (size_t)(n0 + r) * K + k0 + tx;
        Th[o] = h;
        Tl[o] = l;
    }
}

// ---------------------------------------------------------------------------
// Query fp32 -> bf16 hi/lo
// ---------------------------------------------------------------------------
__global__ __launch_bounds__(256) void qconv_kernel(const float* __restrict__ Q) {
    int idx = blockIdx.x * blockDim.x + threadIdx.x;
    float x = Q[idx];
    __nv_bfloat16 h, l;
    split_bf16(x, h, l);
    g_qry_h[idx] = h;
    g_qry_l[idx] = l;
}

// ---------------------------------------------------------------------------
// Fused QKV bias vector: [bq, 0, bv]
// ---------------------------------------------------------------------------
__global__ __launch_bounds__(256) void bias_fuse(const float* __restrict__ bq,
                                                 const float* __restrict__ bv) {
    int i = blockIdx.x * blockDim.x + threadIdx.x;   // 0..1535
    float v = 0.0f;
    if (i < 512) v = bq[i];
    else if (i >= 1024) v = bv[i - 1024];
    g_bqkv[i] = v;
}

// ---------------------------------------------------------------------------
// mma.sync bf16 split GEMM, cp.async double-buffered + ldmatrix fragments.
// Tile 128x128, BK=32, 8 warps (2m x 4n), warp tile 64x32.
// Products hh + hl + lh, product-major MMA order (16 independent MMAs/group).
// epi: 0 = +bias -> Cf ; 1 = silu(+bias) -> (Oh,Ol) bf16 ; 2 = +bias+resid -> Cf
//      3 = fused QKV: +bias(g_bqkv) -> {Cf,C2,C3}[col>>9]
// ---------------------------------------------------------------------------
#define PADB 80                       // bytes per smem tile row (40 bf16)
#define TILEB (128 * PADB)            // 10240 bytes per tile
#define GSMEM (8 * TILEB)             // 4 tiles x 2 stages = 81920 bytes

#define MMA16816(d, a, b) \
    asm volatile( \
        "mma.sync.aligned.m16n8k16.row.col.f32.bf16.bf16.f32 " \
        "{%0,%1,%2,%3}, {%4,%5,%6,%7}, {%8,%9}, {%0,%1,%2,%3};" \
        : "+f"((d)[0]), "+f"((d)[1]), "+f"((d)[2]), "+f"((d)[3]) \
        : "r"((a)[0]), "r"((a)[1]), "r"((a)[2]), "r"((a)[3]), \
          "r"((b)[0]), "r"((b)[1]))

__global__ __launch_bounds__(256) void gemm_mma(
    const __nv_bfloat16* __restrict__ Ah, const __nv_bfloat16* __restrict__ Al,
    const __nv_bfloat16* __restrict__ Bh, const __nv_bfloat16* __restrict__ Bl,
    const float* __restrict__ bias, const float* __restrict__ resid,
    float* __restrict__ Cf, float* __restrict__ C2, float* __restrict__ C3,
    __nv_bfloat16* __restrict__ Oh, __nv_bfloat16* __restrict__ Ol,
    int K, int epi)
{
    extern __shared__ char smem[];
    uint32_t sbase = smem_u32(smem);

    int t = threadIdx.x, lane = t & 31, wid = t >> 5;
    int wm = wid >> 2;        // 0..1 -> m offset wm*64
    int wn = wid & 3;         // 0..3 -> n offset wn*32
    int m0 = blockIdx.y * 128, n0 = blockIdx.x * 128;

    float acc[4][4][4];
#pragma unroll
    for (int mi = 0; mi < 4; mi++)
#pragma unroll
        for (int ni = 0; ni < 4; ni++)
#pragma unroll
            for (int j = 0; j < 4; j++) acc[mi][ni][j] = 0.0f;

    int ldrow0 = t >> 2,         ldc0 = t & 3;
    int ldrow1 = (t + 256) >> 2, ldc1 = (t + 256) & 3;

    int nch = K >> 5;

    auto load_chunk = [&](int ch, int buf) {
        int k0 = ch << 5;
        {
            uint32_t off = (uint32_t)(ldrow0 * PADB + ldc0 * 16);
            cp16(sbase + (0 * 2 + buf) * TILEB + off, Ah + (size_t)(m0 + ldrow0) * K + k0 + ldc0 * 8);
            cp16(sbase + (1 * 2 + buf) * TILEB + off, Al + (size_t)(m0 + ldrow0) * K + k0 + ldc0 * 8);
            cp16(sbase + (2 * 2 + buf) * TILEB + off, Bh + (size_t)(n0 + ldrow0) * K + k0 + ldc0 * 8);
            cp16(sbase + (3 * 2 + buf) * TILEB + off, Bl + (size_t)(n0 + ldrow0) * K + k0 + ldc0 * 8);
        }
        {
            uint32_t off = (uint32_t)(ldrow1 * PADB + ldc1 * 16);
            cp16(sbase + (0 * 2 + buf) * TILEB + off, Ah + (size_t)(m0 + ldrow1) * K + k0 + ldc1 * 8);
            cp16(sbase + (1 * 2 + buf) * TILEB + off, Al + (size_t)(m0 + ldrow1) * K + k0 + ldc1 * 8);
            cp16(sbase + (2 * 2 + buf) * TILEB + off, Bh + (size_t)(n0 + ldrow1) * K + k0 + ldc1 * 8);
            cp16(sbase + (3 * 2 + buf) * TILEB + off, Bl + (size_t)(n0 + ldrow1) * K + k0 + ldc1 * 8);
        }
        CP_COMMIT();
    };

    int g  = lane >> 3, lr = lane & 7;
    uint32_t arow = (uint32_t)((wm * 64 + (g & 1) * 8 + lr) * PADB + ((g >> 1) * 16));
    uint32_t brow = (uint32_t)((wn * 32 + (g >> 1) * 8 + lr) * PADB + ((g & 1) * 16));

    load_chunk(0, 0);
    load_chunk(1, 1);

    for (int ch = 0; ch < nch; ch++) {
        if (ch + 1 < nch) { CP_WAIT(1); } else { CP_WAIT(0); }
        __syncthreads();

        int buf = ch & 1;
        uint32_t aAh = sbase + (0 * 2 + buf) * TILEB;
        uint32_t aAl = sbase + (1 * 2 + buf) * TILEB;
        uint32_t aBh = sbase + (2 * 2 + buf) * TILEB;
        uint32_t aBl = sbase + (3 * 2 + buf) * TILEB;

#pragma unroll
        for (int ks = 0; ks < 2; ks++) {
            uint32_t koff = (uint32_t)(ks * 32);
            uint32_t ah[4][4], al[4][4], bh[4][2], bl[4][2];
#pragma unroll
            for (int mi = 0; mi < 4; mi++) {
                ldsm4(aAh + arow + mi * (16 * PADB) + koff,
                      ah[mi][0], ah[mi][1], ah[mi][2], ah[mi][3]);
                ldsm4(aAl + arow + mi * (16 * PADB) + koff,
                      al[mi][0], al[mi][1], al[mi][2], al[mi][3]);
            }
#pragma unroll
            for (int np = 0; np < 2; np++) {
                ldsm4(aBh + brow + np * (16 * PADB) + koff,
                      bh[2*np][0], bh[2*np][1], bh[2*np+1][0], bh[2*np+1][1]);
                ldsm4(aBl + brow + np * (16 * PADB) + koff,
                      bl[2*np][0], bl[2*np][1], bl[2*np+1][0], bl[2*np+1][1]);
            }
            // product-major: 16 independent MMAs per group (RAW distance 16)
#pragma unroll
            for (int mi = 0; mi < 4; mi++)
#pragma unroll
                for (int ni = 0; ni < 4; ni++)
                    MMA16816(acc[mi][ni], ah[mi], bh[ni]);   // hi*hi
#pragma unroll
            for (int mi = 0; mi < 4; mi++)
#pragma unroll
                for (int ni = 0; ni < 4; ni++)
                    MMA16816(acc[mi][ni], ah[mi], bl[ni]);   // hi*lo
#pragma unroll
            for (int mi = 0; mi < 4; mi++)
#pragma unroll
                for (int ni = 0; ni < 4; ni++)
                    MMA16816(acc[mi][ni], al[mi], bh[ni]);   // lo*hi
        }
        __syncthreads();
        if (ch + 2 < nch) load_chunk(ch + 2, buf);
    }

    // Epilogue
    int gr = lane >> 2, gc = lane & 3;
#pragma unroll
    for (int mi = 0; mi < 4; mi++) {
#pragma unroll
        for (int ni = 0; ni < 4; ni++) {
            int row0 = m0 + wm * 64 + mi * 16 + gr;
            int col  = n0 + wn * 32 + ni * 8 + gc * 2;
#pragma unroll
            for (int half = 0; half < 2; half++) {
                int row = row0 + half * 8;
                float v0 = acc[mi][ni][half * 2 + 0];
                float v1 = acc[mi][ni][half * 2 + 1];
                if (bias) { v0 += bias[col]; v1 += bias[col + 1]; }
                if (epi == 1) {
                    v0 = v0 / (1.0f + expf(-v0));
                    v1 = v1 / (1.0f + expf(-v1));
                    __nv_bfloat16 h0, l0, h1, l1;
                    split_bf16(v0, h0, l0);
                    split_bf16(v1, h1, l1);
                    size_t o = (size_t)row * CC + col;
                    Oh[o] = h0; Oh[o + 1] = h1;
                    Ol[o] = l0; Ol[o + 1] = l1;
                } else if (epi == 3) {
                    int seg = col >> 9;
                    float* dst = (seg == 0) ? Cf : (seg == 1) ? C2 : C3;
                    size_t o = (size_t)row * CC + (col & 511);
                    *(float2*)(dst + o) = make_float2(v0, v1);
                } else {
                    size_t o = (size_t)row * CC + col;
                    if (epi == 2) {
                        v0 += resid[o];
                        v1 += resid[o + 1];
                    }
                    *(float2*)(Cf + o) = make_float2(v0, v1);
                }
            }
        }
    }
}

// ---------------------------------------------------------------------------
// Fused attention, 4 batches per block: grid (16 bgroups, 8 heads).
// ---------------------------------------------------------------------------
#define ATTN_SMEM (4 * 64 * 68 * 4)

__global__ __launch_bounds__(256, 1) void attn_kernel() {
    extern __shared__ float kv[];      // staging: [4][64][68]
    __shared__ float qrow[4][64];
    __shared__ float s[4][64];

    int h   = blockIdx.y;
    int bg0 = blockIdx.x * 4;
    int t   = threadIdx.x;
    int bh  = t >> 6;
    int i   = t & 63;

    float kreg[64], vreg[64];

#pragma unroll
    for (int it = 0; it < 16; it++) {
        int slot = t + it * 256;
        int b  = slot >> 10;
        int m  = (slot >> 4) & 63;
        int d4 = slot & 15;
        float4 x = *(const float4*)(g_k + ((size_t)((bg0 + b) * 64 + m)) * 512 + h * 64 + d4 * 4);
        *(float4*)&kv[(b * 64 + m) * 68 + d4 * 4] = x;
    }
    __syncthreads();
#pragma unroll
    for (int d = 0; d < 64; d++) kreg[d] = kv[(bh * 64 + i) * 68 + d];
    __syncthreads();

#pragma unroll
    for (int it = 0; it < 16; it++) {
        int slot = t + it * 256;
        int b  = slot >> 10;
        int m  = (slot >> 4) & 63;
        int d4 = slot & 15;
        float4 x = *(const float4*)(g_v + ((size_t)((bg0 + b) * 64 + m)) * 512 + h * 64 + d4 * 4);
        *(float4*)&kv[(b * 64 + m) * 68 + d4 * 4] = x;
    }
    __syncthreads();
#pragma unroll
    for (int m = 0; m < 64; m++) vreg[m] = kv[(bh * 64 + m) * 68 + i];
    __syncthreads();

    for (int n = 0; n < 64; n++) {
        if (t < 64) {
            int b = t >> 4, w = t & 15;
            float4 qv = *(const float4*)(g_q + ((size_t)((bg0 + b) * 64 + n)) * 512 + h * 64 + w * 4);
            *(float4*)&qrow[b][w * 4] = qv;
        }
        __syncthreads();

        const float* pep = g_pe + ((size_t)(n * 64 + i)) * 512 + h * 64;
        float p = 0.0f;
#pragma unroll
        for (int d4 = 0; d4 < 16; d4++) {
            float4 pe4 = *(const float4*)(pep + d4 * 4);
            int d = d4 * 4;
            p = fmaf(qrow[bh][d + 0] * kreg[d + 0], pe4.x, p);
            p = fmaf(qrow[bh][d + 1] * kreg[d + 1], pe4.y, p);
            p = fmaf(qrow[bh][d + 2] * kreg[d + 2], pe4.z, p);
            p = fmaf(qrow[bh][d + 3] * kreg[d + 3], pe4.w, p);
        }
        s[bh][i] = p * 0.125f;
        __syncthreads();

        if (t < 128) {
            int w = t >> 5, lane = t & 31;
            float a  = s[w][lane];
            float c2 = s[w][lane + 32];
            float mx = fmaxf(a, c2);
#pragma unroll
            for (int off = 16; off > 0; off >>= 1)
                mx = fmaxf(mx, __shfl_xor_sync(0xffffffffu, mx, off));
            float e1 = __expf(a - mx), e2 = __expf(c2 - mx);
            float sm = e1 + e2;
#pragma unroll
            for (int off = 16; off > 0; off >>= 1)
                sm += __shfl_xor_sync(0xffffffffu, sm, off);
            float inv = 1.0f / sm;
            s[w][lane]      = e1 * inv;
            s[w][lane + 32] = e2 * inv;
        }
        __syncthreads();

        float xv = 0.0f;
#pragma unroll
        for (int m = 0; m < 64; m++)
            xv = fmaf(s[bh][m], vreg[m], xv);
        __nv_bfloat16 hh, ll;
        split_bf16(xv, hh, ll);
        size_t o = ((size_t)((bg0 + bh) * 64 + n)) * 512 + h * 64 + i;
        g_x_h[o] = hh;
        g_x_l[o] = ll;
        __syncthreads();
    }
}

// ---------------------------------------------------------------------------
// Launch
// ---------------------------------------------------------------------------
extern "C" void kernel_launch(void* const* d_in, const int* in_sizes, int n_in,
                              void* d_out, int out_size)
{
    const float* query = (const float*)d_in[0];
    const float* qpos  = (const float*)d_in[1];
    const float* Wq    = (const float*)d_in[2];
    const float* bq    = (const float*)d_in[3];
    const float* Wk    = (const float*)d_in[4];
    const float* Wv    = (const float*)d_in[5];
    const float* bv    = (const float*)d_in[6];
    const float* Wo    = (const float*)d_in[7];
    const float* bo    = (const float*)d_in[8];
    const float* W1    = (const float*)d_in[9];
    const float* b1    = (const float*)d_in[10];
    const float* W2    = (const float*)d_in[11];
    const float* b2    = (const float*)d_in[12];
    float* out = (float*)d_out;

    cudaFuncSetAttribute(gemm_mma, cudaFuncAttributeMaxDynamicSharedMemorySize, GSMEM);
    cudaFuncSetAttribute(attn_kernel, cudaFuncAttributeMaxDynamicSharedMemorySize, ATTN_SMEM);

    void *p_pe, *p_q, *p_k, *p_v, *p_bqkv;
    void *p_embh, *p_embl, *p_hidh, *p_hidl, *p_qryh, *p_qryl, *p_xh, *p_xl;
    void *p_wh, *p_wl;
    cudaGetSymbolAddress(&p_pe,   g_pe);
    cudaGetSymbolAddress(&p_q,    g_q);
    cudaGetSymbolAddress(&p_k,    g_k);
    cudaGetSymbolAddress(&p_v,    g_v);
    cudaGetSymbolAddress(&p_bqkv, g_bqkv);
    cudaGetSymbolAddress(&p_embh, g_emb_h);
    cudaGetSymbolAddress(&p_embl, g_emb_l);
    cudaGetSymbolAddress(&p_hidh, g_hid_h);
    cudaGetSymbolAddress(&p_hidl, g_hid_l);
    cudaGetSymbolAddress(&p_qryh, g_qry_h);
    cudaGetSymbolAddress(&p_qryl, g_qry_l);
    cudaGetSymbolAddress(&p_xh,   g_x_h);
    cudaGetSymbolAddress(&p_xl,   g_x_l);
    cudaGetSymbolAddress(&p_wh,   g_w_h);
    cudaGetSymbolAddress(&p_wl,   g_w_l);

    __nv_bfloat16* wh = (__nv_bfloat16*)p_wh;
    __nv_bfloat16* wl = (__nv_bfloat16*)p_wl;
    const int WSLOT = CC * CC;
    // slots: 0=W1t(512x256), 1=W2t, 2=Wqt, 3=Wkt, 4=Wvt, 5=Wot

    // launch 1: embedding
    embed_kernel<<<4096, 256>>>(qpos);
    // launch 2: all weight transposes
    wconv_all<<<dim3(16, 16, 6), 256>>>(W1, W2, Wq, Wk, Wv, Wo);
    // launch 3: query -> bf16 hi/lo
    qconv_kernel<<<ROWS * CC / 256, 256>>>(query);
    // launch 4: fused qkv bias
    bias_fuse<<<6, 256>>>(bq, bv);

    dim3 gg(4, 32);

    // launch 5: MLP1 (K=256, SiLU)
    gemm_mma<<<gg, 256, GSMEM>>>(
        (const __nv_bfloat16*)p_embh, (const __nv_bfloat16*)p_embl,
        wh + 0 * WSLOT, wl + 0 * WSLOT, b1, nullptr,
        nullptr, nullptr, nullptr,
        (__nv_bfloat16*)p_hidh, (__nv_bfloat16*)p_hidl, FREQE, 1);
    // launch 6 (ncu-profiled): MLP2 (K=512)
    gemm_mma<<<gg, 256, GSMEM>>>(
        (const __nv_bfloat16*)p_hidh, (const __nv_bfloat16*)p_hidl,
        wh + 1 * WSLOT, wl + 1 * WSLOT, b2, nullptr,
        (float*)p_pe, nullptr, nullptr, nullptr, nullptr, CC, 0);
    // launch 7: fused QKV (N=1536)
    gemm_mma<<<dim3(12, 32), 256, GSMEM>>>(
        (const __nv_bfloat16*)p_qryh, (const __nv_bfloat16*)p_qryl,
        wh + 2 * WSLOT, wl + 2 * WSLOT, (const float*)p_bqkv, nullptr,
        (float*)p_q, (float*)p_k, (float*)p_v, nullptr, nullptr, CC, 3);
    // launch 8: attention
    attn_kernel<<<dim3(16, HH), 256, ATTN_SMEM>>>();
    // launch 9: output projection + residual
    gemm_mma<<<gg, 256, GSMEM>>>(
        (const __nv_bfloat16*)p_xh, (const __nv_bfloat16*)p_xl,
        wh + 5 * WSLOT, wl + 5 * WSLOT, bo, query,
        out, nullptr, nullptr, nullptr, nullptr, CC, 2);
}

// round 6
// speedup vs baseline: 2.1716x; 1.1377x over previous
#include <cuda_runtime.h>
#include <cuda_bf16.h>
#include <math.h>
#include <stdint.h>

// Problem constants
#define BB    64
#define CC    512
#define HH    8
#define HD    64
#define FREQE 256
#define ROWS  4096   // B*N == N*M

// ---------------------------------------------------------------------------
// Scratch (device globals; no allocation allowed)
// ---------------------------------------------------------------------------
__device__ float g_pe [ROWS * CC];
__device__ float g_q  [ROWS * CC];
__device__ float g_k  [ROWS * CC];
__device__ float g_v  [ROWS * CC];
__device__ float g_emb[ROWS * FREQE];
__device__ float g_hid[ROWS * CC];
__device__ float g_bqkv[3 * CC];
__device__ float g_wt [5 * CC * CC];            // fp32 transposed W1,W2,Wq,Wk,Wv

__device__ __nv_bfloat16 g_x_h[ROWS * CC];
__device__ __nv_bfloat16 g_x_l[ROWS * CC];
__device__ __nv_bfloat16 g_wo_h[CC * CC];       // Wo transposed, bf16 hi
__device__ __nv_bfloat16 g_wo_l[CC * CC];       // Wo transposed, bf16 lo

__device__ __forceinline__ void split_bf16(float x, __nv_bfloat16& h, __nv_bfloat16& l) {
    h = __float2bfloat16(x);
    l = __float2bfloat16(x - __bfloat162float(h));
}

__device__ __forceinline__ uint32_t smem_u32(const void* p) {
    uint32_t a;
    asm("{ .reg .u64 t; cvta.to.shared.u64 t, %1; cvt.u32.u64 %0, t; }"
        : "=r"(a) : "l"(p));
    return a;
}

__device__ __forceinline__ void cp16(uint32_t dst, const void* src) {
    asm volatile("cp.async.cg.shared.global [%0], [%1], 16;" :: "r"(dst), "l"(src));
}
#define CP_COMMIT() asm volatile("cp.async.commit_group;" ::: "memory")
#define CP_WAIT(n)  asm volatile("cp.async.wait_group %0;" :: "n"(n) : "memory")

__device__ __forceinline__ void ldsm4(uint32_t addr, uint32_t& r0, uint32_t& r1,
                                      uint32_t& r2, uint32_t& r3) {
    asm volatile("ldmatrix.sync.aligned.m8n8.x4.shared.b16 {%0,%1,%2,%3}, [%4];"
        : "=r"(r0), "=r"(r1), "=r"(r2), "=r"(r3) : "r"(addr));
}

__device__ __forceinline__ uint32_t to_tf32(float x) {
    uint32_t u;
    asm("cvt.rna.tf32.f32 %0, %1;" : "=r"(u) : "f"(x));
    return u;
}

// ---------------------------------------------------------------------------
// Sinusoidal embedding -> fp32
// ---------------------------------------------------------------------------
__global__ __launch_bounds__(256) void embed_kernel(const float* __restrict__ qpos) {
    int idx = blockIdx.x * blockDim.x + threadIdx.x;
    int p = idx >> 8;
    int j = idx & 255;
    float t = qpos[p];
    int jj = j & 127;
    float f = expf(-9.210340371976184f * (float)jj * (1.0f / 128.0f));
    float a = t * f;
    g_emb[idx] = (j < 128) ? cosf(a) : sinf(a);
}

// ---------------------------------------------------------------------------
// All weight transposes in ONE launch.
// slot 0..4 -> fp32 transposed (W1 K=256, W2/Wq/Wk/Wv K=512)
// slot 5    -> Wo transposed bf16 hi/lo
// ---------------------------------------------------------------------------
__global__ __launch_bounds__(256) void wconv_all(
    const float* __restrict__ W1, const float* __restrict__ W2,
    const float* __restrict__ Wq, const float* __restrict__ Wk,
    const float* __restrict__ Wv, const float* __restrict__ Wo)
{
    __shared__ float sm[32][33];
    int slot = blockIdx.z;
    int K = (slot == 0) ? FREQE : CC;
    int k0 = blockIdx.x * 32, n0 = blockIdx.y * 32;
    if (k0 >= K) return;

    const float* W = (slot == 0) ? W1 : (slot == 1) ? W2 : (slot == 2) ? Wq
                   : (slot == 3) ? Wk : (slot == 4) ? Wv : Wo;

    int t = threadIdx.x;
    int tx = t & 31, ty = t >> 5;
#pragma unroll
    for (int i = 0; i < 4; i++) {
        int r = ty + i * 8;
        sm[r][tx] = W[(size_t)(k0 + r) * CC + n0 + tx];
    }
    __syncthreads();
#pragma unroll
    for (int i = 0; i < 4; i++) {
        int r = ty + i * 8;
        float x = sm[tx][r];
        if (slot < 5) {
            g_wt[(size_t)slot * CC * CC + (size_t)(n0 + r) * K + k0 + tx] = x;
        } else {
            __nv_bfloat16 h, l;
            split_bf16(x, h, l);
            size_t o = (size_t)(n0 + r) * CC + k0 + tx;
            g_wo_h[o] = h;
            g_wo_l[o] = l;
        }
    }
}

// ---------------------------------------------------------------------------
// Fused QKV bias vector: [bq, 0, bv]
// ---------------------------------------------------------------------------
__global__ __launch_bounds__(256) void bias_fuse(const float* __restrict__ bq,
                                                 const float* __restrict__ bv) {
    int i = blockIdx.x * blockDim.x + threadIdx.x;
    float v = 0.0f;
    if (i < 512) v = bq[i];
    else if (i >= 1024) v = bv[i - 1024];
    g_bqkv[i] = v;
}

// ---------------------------------------------------------------------------
// 1xTF32 GEMM: C[M,N] = A[M,K] @ Bt^T  (A fp32 row-major, Bt fp32 [N,K]).
// Tile 128x128, BK=32, 8 warps (2m x 4n), mma m16n8k8.tf32, fp32 accum.
// epi: 0 = +bias -> Cf ; 1 = silu(+bias) -> Cf ; 3 = QKV split {Cf,C2,C3}
// ---------------------------------------------------------------------------
#define TPAD 36                         // floats per smem row (32 data + 4 pad)
#define TTILE (128 * TPAD * 4)          // 18432 bytes per tile
#define TSMEM (4 * TTILE)               // A,B x 2 stages = 73728 bytes

#define MMA1688T(d, a, b) \
    asm volatile( \
        "mma.sync.aligned.m16n8k8.row.col.f32.tf32.tf32.f32 " \
        "{%0,%1,%2,%3}, {%4,%5,%6,%7}, {%8,%9}, {%0,%1,%2,%3};" \
        : "+f"((d)[0]), "+f"((d)[1]), "+f"((d)[2]), "+f"((d)[3]) \
        : "r"((a)[0]), "r"((a)[1]), "r"((a)[2]), "r"((a)[3]), \
          "r"((b)[0]), "r"((b)[1]))

__global__ __launch_bounds__(256) void gemm_tf32(
    const float* __restrict__ A, const float* __restrict__ Bt,
    const float* __restrict__ bias,
    float* __restrict__ Cf, float* __restrict__ C2, float* __restrict__ C3,
    int K, int epi)
{
    extern __shared__ float smf[];
    uint32_t sbase = smem_u32(smf);

    int t = threadIdx.x, lane = t & 31, wid = t >> 5;
    int wm = wid >> 2;        // 0..1
    int wn = wid & 3;         // 0..3
    int m0 = blockIdx.y * 128, n0 = blockIdx.x * 128;
    int gr = lane >> 2, gc = lane & 3;

    float acc[4][4][4];
#pragma unroll
    for (int mi = 0; mi < 4; mi++)
#pragma unroll
        for (int ni = 0; ni < 4; ni++)
#pragma unroll
            for (int j = 0; j < 4; j++) acc[mi][ni][j] = 0.0f;

    int nch = K >> 5;

    // stage loader: tiles A (idx 0) and B (idx 1), 2 stages
    auto load_chunk = [&](int ch, int buf) {
        int k0 = ch << 5;
#pragma unroll
        for (int i = 0; i < 4; i++) {
            int idx = t + i * 256;          // 0..1023
            int row = idx >> 3;             // 0..127
            int c   = idx & 7;              // 16B chunk within 32-float row
            uint32_t off = (uint32_t)(row * TPAD * 4 + c * 16);
            cp16(sbase + (0 * 2 + buf) * TTILE + off,
                 A  + (size_t)(m0 + row) * K + k0 + c * 4);
            cp16(sbase + (1 * 2 + buf) * TTILE + off,
                 Bt + (size_t)(n0 + row) * K + k0 + c * 4);
        }
        CP_COMMIT();
    };

    load_chunk(0, 0);
    load_chunk(1, 1);

    for (int ch = 0; ch < nch; ch++) {
        if (ch + 1 < nch) { CP_WAIT(1); } else { CP_WAIT(0); }
        __syncthreads();

        int buf = ch & 1;
        const float* sA = smf + ((0 * 2 + buf) * TTILE >> 2);
        const float* sB = smf + ((1 * 2 + buf) * TTILE >> 2);

#pragma unroll
        for (int ks = 0; ks < 4; ks++) {
            int kk = ks * 8;
            uint32_t af[4][4], bf[4][2];
#pragma unroll
            for (int mi = 0; mi < 4; mi++) {
                int base = (wm * 64 + mi * 16 + gr) * TPAD + kk;
                af[mi][0] = to_tf32(sA[base + gc]);
                af[mi][1] = to_tf32(sA[base + 8 * TPAD + gc]);
                af[mi][2] = to_tf32(sA[base + gc + 4]);
                af[mi][3] = to_tf32(sA[base + 8 * TPAD + gc + 4]);
            }
#pragma unroll
            for (int ni = 0; ni < 4; ni++) {
                int base = (wn * 32 + ni * 8 + gr) * TPAD + kk;
                bf[ni][0] = to_tf32(sB[base + gc]);
                bf[ni][1] = to_tf32(sB[base + gc + 4]);
            }
#pragma unroll
            for (int mi = 0; mi < 4; mi++)
#pragma unroll
                for (int ni = 0; ni < 4; ni++)
                    MMA1688T(acc[mi][ni], af[mi], bf[ni]);
        }
        __syncthreads();
        if (ch + 2 < nch) load_chunk(ch + 2, buf);
    }

    // Epilogue: c0,c1 @ (row, col..col+1), c2,c3 @ (row+8, ...)
#pragma unroll
    for (int mi = 0; mi < 4; mi++) {
#pragma unroll
        for (int ni = 0; ni < 4; ni++) {
            int row0 = m0 + wm * 64 + mi * 16 + gr;
            int col  = n0 + wn * 32 + ni * 8 + gc * 2;
#pragma unroll
            for (int half = 0; half < 2; half++) {
                int row = row0 + half * 8;
                float v0 = acc[mi][ni][half * 2 + 0];
                float v1 = acc[mi][ni][half * 2 + 1];
                if (bias) { v0 += bias[col]; v1 += bias[col + 1]; }
                if (epi == 1) {
                    v0 = v0 / (1.0f + expf(-v0));
                    v1 = v1 / (1.0f + expf(-v1));
                }
                if (epi == 3) {
                    int seg = col >> 9;
                    float* dst = (seg == 0) ? Cf : (seg == 1) ? C2 : C3;
                    size_t o = (size_t)row * CC + (col & 511);
                    *(float2*)(dst + o) = make_float2(v0, v1);
                } else {
                    size_t o = (size_t)row * CC + col;
                    *(float2*)(Cf + o) = make_float2(v0, v1);
                }
            }
        }
    }
}

// ---------------------------------------------------------------------------
// bf16 split GEMM (3-product) — used only for the output projection.
// ---------------------------------------------------------------------------
#define PADB 80
#define TILEB (128 * PADB)
#define GSMEM (8 * TILEB)

#define MMA16816(d, a, b) \
    asm volatile( \
        "mma.sync.aligned.m16n8k16.row.col.f32.bf16.bf16.f32 " \
        "{%0,%1,%2,%3}, {%4,%5,%6,%7}, {%8,%9}, {%0,%1,%2,%3};" \
        : "+f"((d)[0]), "+f"((d)[1]), "+f"((d)[2]), "+f"((d)[3]) \
        : "r"((a)[0]), "r"((a)[1]), "r"((a)[2]), "r"((a)[3]), \
          "r"((b)[0]), "r"((b)[1]))

__global__ __launch_bounds__(256) void gemm_mma(
    const __nv_bfloat16* __restrict__ Ah, const __nv_bfloat16* __restrict__ Al,
    const __nv_bfloat16* __restrict__ Bh, const __nv_bfloat16* __restrict__ Bl,
    const float* __restrict__ bias, const float* __restrict__ resid,
    float* __restrict__ Cf, int K)
{
    extern __shared__ char smem[];
    uint32_t sbase = smem_u32(smem);

    int t = threadIdx.x, lane = t & 31, wid = t >> 5;
    int wm = wid >> 2, wn = wid & 3;
    int m0 = blockIdx.y * 128, n0 = blockIdx.x * 128;

    float acc[4][4][4];
#pragma unroll
    for (int mi = 0; mi < 4; mi++)
#pragma unroll
        for (int ni = 0; ni < 4; ni++)
#pragma unroll
            for (int j = 0; j < 4; j++) acc[mi][ni][j] = 0.0f;

    int ldrow0 = t >> 2,         ldc0 = t & 3;
    int ldrow1 = (t + 256) >> 2, ldc1 = (t + 256) & 3;
    int nch = K >> 5;

    auto load_chunk = [&](int ch, int buf) {
        int k0 = ch << 5;
        {
            uint32_t off = (uint32_t)(ldrow0 * PADB + ldc0 * 16);
            cp16(sbase + (0 * 2 + buf) * TILEB + off, Ah + (size_t)(m0 + ldrow0) * K + k0 + ldc0 * 8);
            cp16(sbase + (1 * 2 + buf) * TILEB + off, Al + (size_t)(m0 + ldrow0) * K + k0 + ldc0 * 8);
            cp16(sbase + (2 * 2 + buf) * TILEB + off, Bh + (size_t)(n0 + ldrow0) * K + k0 + ldc0 * 8);
            cp16(sbase + (3 * 2 + buf) * TILEB + off, Bl + (size_t)(n0 + ldrow0) * K + k0 + ldc0 * 8);
        }
        {
            uint32_t off = (uint32_t)(ldrow1 * PADB + ldc1 * 16);
            cp16(sbase + (0 * 2 + buf) * TILEB + off, Ah + (size_t)(m0 + ldrow1) * K + k0 + ldc1 * 8);
            cp16(sbase + (1 * 2 + buf) * TILEB + off, Al + (size_t)(m0 + ldrow1) * K + k0 + ldc1 * 8);
            cp16(sbase + (2 * 2 + buf) * TILEB + off, Bh + (size_t)(n0 + ldrow1) * K + k0 + ldc1 * 8);
            cp16(sbase + (3 * 2 + buf) * TILEB + off, Bl + (size_t)(n0 + ldrow1) * K + k0 + ldc1 * 8);
        }
        CP_COMMIT();
    };

    int g  = lane >> 3, lr = lane & 7;
    uint32_t arow = (uint32_t)((wm * 64 + (g & 1) * 8 + lr) * PADB + ((g >> 1) * 16));
    uint32_t brow = (uint32_t)((wn * 32 + (g >> 1) * 8 + lr) * PADB + ((g & 1) * 16));

    load_chunk(0, 0);
    load_chunk(1, 1);

    for (int ch = 0; ch < nch; ch++) {
        if (ch + 1 < nch) { CP_WAIT(1); } else { CP_WAIT(0); }
        __syncthreads();

        int buf = ch & 1;
        uint32_t aAh = sbase + (0 * 2 + buf) * TILEB;
        uint32_t aAl = sbase + (1 * 2 + buf) * TILEB;
        uint32_t aBh = sbase + (2 * 2 + buf) * TILEB;
        uint32_t aBl = sbase + (3 * 2 + buf) * TILEB;

#pragma unroll
        for (int ks = 0; ks < 2; ks++) {
            uint32_t koff = (uint32_t)(ks * 32);
            uint32_t ah[4][4], al[4][4], bh[4][2], bl[4][2];
#pragma unroll
            for (int mi = 0; mi < 4; mi++) {
                ldsm4(aAh + arow + mi * (16 * PADB) + koff,
                      ah[mi][0], ah[mi][1], ah[mi][2], ah[mi][3]);
                ldsm4(aAl + arow + mi * (16 * PADB) + koff,
                      al[mi][0], al[mi][1], al[mi][2], al[mi][3]);
            }
#pragma unroll
            for (int np = 0; np < 2; np++) {
                ldsm4(aBh + brow + np * (16 * PADB) + koff,
                      bh[2*np][0], bh[2*np][1], bh[2*np+1][0], bh[2*np+1][1]);
                ldsm4(aBl + brow + np * (16 * PADB) + koff,
                      bl[2*np][0], bl[2*np][1], bl[2*np+1][0], bl[2*np+1][1]);
            }
#pragma unroll
            for (int mi = 0; mi < 4; mi++)
#pragma unroll
                for (int ni = 0; ni < 4; ni++)
                    MMA16816(acc[mi][ni], ah[mi], bh[ni]);
#pragma unroll
            for (int mi = 0; mi < 4; mi++)
#pragma unroll
                for (int ni = 0; ni < 4; ni++)
                    MMA16816(acc[mi][ni], ah[mi], bl[ni]);
#pragma unroll
            for (int mi = 0; mi < 4; mi++)
#pragma unroll
                for (int ni = 0; ni < 4; ni++)
                    MMA16816(acc[mi][ni], al[mi], bh[ni]);
        }
        __syncthreads();
        if (ch + 2 < nch) load_chunk(ch + 2, buf);
    }

    int gr = lane >> 2, gc = lane & 3;
#pragma unroll
    for (int mi = 0; mi < 4; mi++) {
#pragma unroll
        for (int ni = 0; ni < 4; ni++) {
            int row0 = m0 + wm * 64 + mi * 16 + gr;
            int col  = n0 + wn * 32 + ni * 8 + gc * 2;
#pragma unroll
            for (int half = 0; half < 2; half++) {
                int row = row0 + half * 8;
                float v0 = acc[mi][ni][half * 2 + 0] + bias[col];
                float v1 = acc[mi][ni][half * 2 + 1] + bias[col + 1];
                size_t o = (size_t)row * CC + col;
                v0 += resid[o];
                v1 += resid[o + 1];
                *(float2*)(Cf + o) = make_float2(v0, v1);
            }
        }
    }
}

// ---------------------------------------------------------------------------
// Fused attention, 4 batches per block: grid (16 bgroups, 8 heads).
// ---------------------------------------------------------------------------
#define ATTN_SMEM (4 * 64 * 68 * 4)

__global__ __launch_bounds__(256, 1) void attn_kernel() {
    extern __shared__ float kv[];      // staging: [4][64][68]
    __shared__ float qrow[4][64];
    __shared__ float s[4][64];

    int h   = blockIdx.y;
    int bg0 = blockIdx.x * 4;
    int t   = threadIdx.x;
    int bh  = t >> 6;
    int i   = t & 63;

    float kreg[64], vreg[64];

#pragma unroll
    for (int it = 0; it < 16; it++) {
        int slot = t + it * 256;
        int b  = slot >> 10;
        int m  = (slot >> 4) & 63;
        int d4 = slot & 15;
        float4 x = *(const float4*)(g_k + ((size_t)((bg0 + b) * 64 + m)) * 512 + h * 64 + d4 * 4);
        *(float4*)&kv[(b * 64 + m) * 68 + d4 * 4] = x;
    }
    __syncthreads();
#pragma unroll
    for (int d = 0; d < 64; d++) kreg[d] = kv[(bh * 64 + i) * 68 + d];
    __syncthreads();

#pragma unroll
    for (int it = 0; it < 16; it++) {
        int slot = t + it * 256;
        int b  = slot >> 10;
        int m  = (slot >> 4) & 63;
        int d4 = slot & 15;
        float4 x = *(const float4*)(g_v + ((size_t)((bg0 + b) * 64 + m)) * 512 + h * 64 + d4 * 4);
        *(float4*)&kv[(b * 64 + m) * 68 + d4 * 4] = x;
    }
    __syncthreads();
#pragma unroll
    for (int m = 0; m < 64; m++) vreg[m] = kv[(bh * 64 + m) * 68 + i];
    __syncthreads();

    for (int n = 0; n < 64; n++) {
        if (t < 64) {
            int b = t >> 4, w = t & 15;
            float4 qv = *(const float4*)(g_q + ((size_t)((bg0 + b) * 64 + n)) * 512 + h * 64 + w * 4);
            *(float4*)&qrow[b][w * 4] = qv;
        }
        __syncthreads();

        const float* pep = g_pe + ((size_t)(n * 64 + i)) * 512 + h * 64;
        float p = 0.0f;
#pragma unroll
        for (int d4 = 0; d4 < 16; d4++) {
            float4 pe4 = *(const float4*)(pep + d4 * 4);
            int d = d4 * 4;
            p = fmaf(qrow[bh][d + 0] * kreg[d + 0], pe4.x, p);
            p = fmaf(qrow[bh][d + 1] * kreg[d + 1], pe4.y, p);
            p = fmaf(qrow[bh][d + 2] * kreg[d + 2], pe4.z, p);
            p = fmaf(qrow[bh][d + 3] * kreg[d + 3], pe4.w, p);
        }
        s[bh][i] = p * 0.125f;
        __syncthreads();

        if (t < 128) {
            int w = t >> 5, lane = t & 31;
            float a  = s[w][lane];
            float c2 = s[w][lane + 32];
            float mx = fmaxf(a, c2);
#pragma unroll
            for (int off = 16; off > 0; off >>= 1)
                mx = fmaxf(mx, __shfl_xor_sync(0xffffffffu, mx, off));
            float e1 = __expf(a - mx), e2 = __expf(c2 - mx);
            float sm = e1 + e2;
#pragma unroll
            for (int off = 16; off > 0; off >>= 1)
                sm += __shfl_xor_sync(0xffffffffu, sm, off);
            float inv = 1.0f / sm;
            s[w][lane]      = e1 * inv;
            s[w][lane + 32] = e2 * inv;
        }
        __syncthreads();

        float xv = 0.0f;
#pragma unroll
        for (int m = 0; m < 64; m++)
            xv = fmaf(s[bh][m], vreg[m], xv);
        __nv_bfloat16 hh, ll;
        split_bf16(xv, hh, ll);
        size_t o = ((size_t)((bg0 + bh) * 64 + n)) * 512 + h * 64 + i;
        g_x_h[o] = hh;
        g_x_l[o] = ll;
        __syncthreads();
    }
}

// ---------------------------------------------------------------------------
// Launch — graph with parallel branches:
//   main: wconv + bias ──ew──┐
//   s1:   embed ──(ew)── MLP1 ── MLP2 ──e1──┐
//   s2:   (ew) ── QKV ──e2──────────────────┼── attn ── out  (main)
// ---------------------------------------------------------------------------
extern "C" void kernel_launch(void* const* d_in, const int* in_sizes, int n_in,
                              void* d_out, int out_size)
{
    const float* query = (const float*)d_in[0];
    const float* qpos  = (const float*)d_in[1];
    const float* Wq    = (const float*)d_in[2];
    const float* bq    = (const float*)d_in[3];
    const float* Wk    = (const float*)d_in[4];
    const float* Wv    = (const float*)d_in[5];
    const float* bv    = (const float*)d_in[6];
    const float* Wo    = (const float*)d_in[7];
    const float* bo    = (const float*)d_in[8];
    const float* W1    = (const float*)d_in[9];
    const float* b1    = (const float*)d_in[10];
    const float* W2    = (const float*)d_in[11];
    const float* b2    = (const float*)d_in[12];
    float* out = (float*)d_out;

    static cudaStream_t s1 = nullptr, s2 = nullptr;
    static cudaEvent_t e0 = nullptr, ew = nullptr, e1 = nullptr, e2 = nullptr;
    if (!s1) {
        cudaStreamCreateWithFlags(&s1, cudaStreamNonBlocking);
        cudaStreamCreateWithFlags(&s2, cudaStreamNonBlocking);
        cudaEventCreateWithFlags(&e0, cudaEventDisableTiming);
        cudaEventCreateWithFlags(&ew, cudaEventDisableTiming);
        cudaEventCreateWithFlags(&e1, cudaEventDisableTiming);
        cudaEventCreateWithFlags(&e2, cudaEventDisableTiming);
        cudaFuncSetAttribute(gemm_tf32, cudaFuncAttributeMaxDynamicSharedMemorySize, TSMEM);
        cudaFuncSetAttribute(gemm_mma,  cudaFuncAttributeMaxDynamicSharedMemorySize, GSMEM);
        cudaFuncSetAttribute(attn_kernel, cudaFuncAttributeMaxDynamicSharedMemorySize, ATTN_SMEM);
    }

    void *p_pe, *p_q, *p_k, *p_v, *p_bqkv, *p_emb, *p_hid, *p_wt;
    void *p_xh, *p_xl, *p_woh, *p_wol;
    cudaGetSymbolAddress(&p_pe,   g_pe);
    cudaGetSymbolAddress(&p_q,    g_q);
    cudaGetSymbolAddress(&p_k,    g_k);
    cudaGetSymbolAddress(&p_v,    g_v);
    cudaGetSymbolAddress(&p_bqkv, g_bqkv);
    cudaGetSymbolAddress(&p_emb,  g_emb);
    cudaGetSymbolAddress(&p_hid,  g_hid);
    cudaGetSymbolAddress(&p_wt,   g_wt);
    cudaGetSymbolAddress(&p_xh,   g_x_h);
    cudaGetSymbolAddress(&p_xl,   g_x_l);
    cudaGetSymbolAddress(&p_woh,  g_wo_h);
    cudaGetSymbolAddress(&p_wol,  g_wo_l);

    const float* wt = (const float*)p_wt;
    const int WSLOT = CC * CC;

    // fork
    cudaEventRecord(e0, 0);
    cudaStreamWaitEvent(s1, e0, 0);

    // s1: embedding (independent of weights)
    embed_kernel<<<4096, 256, 0, s1>>>(qpos);

    // main: weight transposes + fused bias
    wconv_all<<<dim3(16, 16, 6), 256>>>(W1, W2, Wq, Wk, Wv, Wo);
    bias_fuse<<<6, 256>>>(bq, bv);
    cudaEventRecord(ew, 0);

    // s1: pe MLP (tf32) after weights ready
    cudaStreamWaitEvent(s1, ew, 0);
    gemm_tf32<<<dim3(4, 32), 256, TSMEM, s1>>>(
        (const float*)p_emb, wt + 0 * WSLOT, b1,
        (float*)p_hid, nullptr, nullptr, FREQE, 1);
    gemm_tf32<<<dim3(4, 32), 256, TSMEM, s1>>>(
        (const float*)p_hid, wt + 1 * WSLOT, b2,
        (float*)p_pe, nullptr, nullptr, CC, 0);
    cudaEventRecord(e1, s1);

    // s2: fused QKV (tf32) straight from fp32 query
    cudaStreamWaitEvent(s2, ew, 0);
    gemm_tf32<<<dim3(12, 32), 256, TSMEM, s2>>>(
        query, wt + 2 * WSLOT, (const float*)p_bqkv,
        (float*)p_q, (float*)p_k, (float*)p_v, CC, 3);
    cudaEventRecord(e2, s2);

    // join -> attention -> output projection
    cudaStreamWaitEvent(0, e1, 0);
    cudaStreamWaitEvent(0, e2, 0);
    attn_kernel<<<dim3(16, HH), 256, ATTN_SMEM>>>();
    gemm_mma<<<dim3(4, 32), 256, GSMEM>>>(
        (const __nv_bfloat16*)p_xh, (const __nv_bfloat16*)p_xl,
        (const __nv_bfloat16*)p_woh, (const __nv_bfloat16*)p_wol,
        bo, query, out, CC);
}

// round 7
// speedup vs baseline: 2.2383x; 1.0307x over previous
#include <cuda_runtime.h>
#include <cuda_bf16.h>
#include <math.h>
#include <stdint.h>

// Problem constants
#define BB    64
#define CC    512
#define HH    8
#define HD    64
#define FREQE 256
#define ROWS  4096   // B*N == N*M

// ---------------------------------------------------------------------------
// Scratch (device globals; no allocation allowed)
// ---------------------------------------------------------------------------
__device__ float g_pe [ROWS * CC];
__device__ float g_q  [ROWS * CC];
__device__ float g_k  [ROWS * CC];
__device__ float g_v  [ROWS * CC];
__device__ float g_x  [ROWS * CC];      // attention output (tf32-rounded)
__device__ float g_emb[ROWS * FREQE];   // tf32-rounded
__device__ float g_hid[ROWS * CC];      // tf32-rounded
__device__ float g_qt [ROWS * CC];      // query tf32-rounded
__device__ float g_bqkv[3 * CC];
__device__ float g_wt [6 * CC * CC];    // tf32-rounded transposed W1,W2,Wq,Wk,Wv,Wo

__device__ __forceinline__ uint32_t to_tf32(float x) {
    uint32_t u;
    asm("cvt.rna.tf32.f32 %0, %1;" : "=r"(u) : "f"(x));
    return u;
}
__device__ __forceinline__ float round_tf32(float x) {
    return __uint_as_float(to_tf32(x));
}

__device__ __forceinline__ uint32_t smem_u32(const void* p) {
    uint32_t a;
    asm("{ .reg .u64 t; cvta.to.shared.u64 t, %1; cvt.u32.u64 %0, t; }"
        : "=r"(a) : "l"(p));
    return a;
}

__device__ __forceinline__ void cp16(uint32_t dst, const void* src) {
    asm volatile("cp.async.cg.shared.global [%0], [%1], 16;" :: "r"(dst), "l"(src));
}
#define CP_COMMIT() asm volatile("cp.async.commit_group;" ::: "memory")
#define CP_WAIT(n)  asm volatile("cp.async.wait_group %0;" :: "n"(n) : "memory")

// ---------------------------------------------------------------------------
// Sinusoidal embedding -> fp32 (tf32-rounded)
// ---------------------------------------------------------------------------
__global__ __launch_bounds__(256) void embed_kernel(const float* __restrict__ qpos) {
    int idx = blockIdx.x * blockDim.x + threadIdx.x;
    int p = idx >> 8;
    int j = idx & 255;
    float t = qpos[p];
    int jj = j & 127;
    float f = expf(-9.210340371976184f * (float)jj * (1.0f / 128.0f));
    float a = t * f;
    float v = (j < 128) ? cosf(a) : sinf(a);
    g_emb[idx] = round_tf32(v);
}

// ---------------------------------------------------------------------------
// Query fp32 -> tf32-rounded
// ---------------------------------------------------------------------------
__global__ __launch_bounds__(256) void qround_kernel(const float* __restrict__ Q) {
    int idx = blockIdx.x * blockDim.x + threadIdx.x;
    g_qt[idx] = round_tf32(Q[idx]);
}

// ---------------------------------------------------------------------------
// All weight transposes (tf32-rounded) + fused bias vector, ONE launch.
// z slots 0..5 = W1(K=256),W2,Wq,Wk,Wv,Wo ; z slot 6 = bias fuse
// ---------------------------------------------------------------------------
__global__ __launch_bounds__(256) void wconv_all(
    const float* __restrict__ W1, const float* __restrict__ W2,
    const float* __restrict__ Wq, const float* __restrict__ Wk,
    const float* __restrict__ Wv, const float* __restrict__ Wo,
    const float* __restrict__ bq, const float* __restrict__ bv)
{
    int slot = blockIdx.z;
    if (slot == 6) {
        int bid = blockIdx.x + blockIdx.y * 16;
        if (bid < 6) {
            int i = bid * 256 + threadIdx.x;   // 0..1535
            float v = 0.0f;
            if (i < 512) v = bq[i];
            else if (i >= 1024) v = bv[i - 1024];
            g_bqkv[i] = v;
        }
        return;
    }

    __shared__ float sm[32][33];
    int K = (slot == 0) ? FREQE : CC;
    int k0 = blockIdx.x * 32, n0 = blockIdx.y * 32;
    if (k0 >= K) return;

    const float* W = (slot == 0) ? W1 : (slot == 1) ? W2 : (slot == 2) ? Wq
                   : (slot == 3) ? Wk : (slot == 4) ? Wv : Wo;

    int t = threadIdx.x;
    int tx = t & 31, ty = t >> 5;
#pragma unroll
    for (int i = 0; i < 4; i++) {
        int r = ty + i * 8;
        sm[r][tx] = W[(size_t)(k0 + r) * CC + n0 + tx];
    }
    __syncthreads();
#pragma unroll
    for (int i = 0; i < 4; i++) {
        int r = ty + i * 8;
        g_wt[(size_t)slot * CC * CC + (size_t)(n0 + r) * K + k0 + tx] =
            round_tf32(sm[tx][r]);
    }
}

// ---------------------------------------------------------------------------
// 1xTF32 GEMM: C[M,N] = A[M,K] @ Bt^T. Inputs PRE-ROUNDED to tf32 —
// inner loop loads raw bits (no cvt). Tile 128x128, BK=32, 8 warps.
// epi: 0 = +bias -> Cf
//      1 = silu(+bias), tf32-rounded -> Cf
//      2 = +bias + resid -> Cf      (final output)
//      3 = +bias(seg), QKV split -> {Cf,C2,C3}
// ---------------------------------------------------------------------------
#define TPAD 36                         // floats per smem row (32 data + 4 pad)
#define TTILE (128 * TPAD * 4)          // bytes per tile
#define TSMEM (4 * TTILE)               // A,B x 2 stages

#define MMA1688T(d, a, b) \
    asm volatile( \
        "mma.sync.aligned.m16n8k8.row.col.f32.tf32.tf32.f32 " \
        "{%0,%1,%2,%3}, {%4,%5,%6,%7}, {%8,%9}, {%0,%1,%2,%3};" \
        : "+f"((d)[0]), "+f"((d)[1]), "+f"((d)[2]), "+f"((d)[3]) \
        : "r"((a)[0]), "r"((a)[1]), "r"((a)[2]), "r"((a)[3]), \
          "r"((b)[0]), "r"((b)[1]))

__global__ __launch_bounds__(256) void gemm_tf32(
    const float* __restrict__ A, const float* __restrict__ Bt,
    const float* __restrict__ bias, const float* __restrict__ resid,
    float* __restrict__ Cf, float* __restrict__ C2, float* __restrict__ C3,
    int K, int epi)
{
    extern __shared__ float smf[];
    uint32_t sbase = smem_u32(smf);

    int t = threadIdx.x, lane = t & 31, wid = t >> 5;
    int wm = wid >> 2;        // 0..1
    int wn = wid & 3;         // 0..3
    int m0 = blockIdx.y * 128, n0 = blockIdx.x * 128;
    int gr = lane >> 2, gc = lane & 3;

    float acc[4][4][4];
#pragma unroll
    for (int mi = 0; mi < 4; mi++)
#pragma unroll
        for (int ni = 0; ni < 4; ni++)
#pragma unroll
            for (int j = 0; j < 4; j++) acc[mi][ni][j] = 0.0f;

    int nch = K >> 5;

    auto load_chunk = [&](int ch, int buf) {
        int k0 = ch << 5;
#pragma unroll
        for (int i = 0; i < 4; i++) {
            int idx = t + i * 256;          // 0..1023
            int row = idx >> 3;             // 0..127
            int c   = idx & 7;              // 16B chunk within 32-float row
            uint32_t off = (uint32_t)(row * TPAD * 4 + c * 16);
            cp16(sbase + (0 * 2 + buf) * TTILE + off,
                 A  + (size_t)(m0 + row) * K + k0 + c * 4);
            cp16(sbase + (1 * 2 + buf) * TTILE + off,
                 Bt + (size_t)(n0 + row) * K + k0 + c * 4);
        }
        CP_COMMIT();
    };

    load_chunk(0, 0);
    load_chunk(1, 1);

    for (int ch = 0; ch < nch; ch++) {
        if (ch + 1 < nch) { CP_WAIT(1); } else { CP_WAIT(0); }
        __syncthreads();

        int buf = ch & 1;
        const uint32_t* sA = (const uint32_t*)(smf + ((0 * 2 + buf) * TTILE >> 2));
        const uint32_t* sB = (const uint32_t*)(smf + ((1 * 2 + buf) * TTILE >> 2));

#pragma unroll
        for (int ks = 0; ks < 4; ks++) {
            int kk = ks * 8;
            uint32_t af[4][4], bf[4][2];
#pragma unroll
            for (int mi = 0; mi < 4; mi++) {
                int base = (wm * 64 + mi * 16 + gr) * TPAD + kk;
                af[mi][0] = sA[base + gc];
                af[mi][1] = sA[base + 8 * TPAD + gc];
                af[mi][2] = sA[base + gc + 4];
                af[mi][3] = sA[base + 8 * TPAD + gc + 4];
            }
#pragma unroll
            for (int ni = 0; ni < 4; ni++) {
                int base = (wn * 32 + ni * 8 + gr) * TPAD + kk;
                bf[ni][0] = sB[base + gc];
                bf[ni][1] = sB[base + gc + 4];
            }
#pragma unroll
            for (int mi = 0; mi < 4; mi++)
#pragma unroll
                for (int ni = 0; ni < 4; ni++)
                    MMA1688T(acc[mi][ni], af[mi], bf[ni]);
        }
        __syncthreads();
        if (ch + 2 < nch) load_chunk(ch + 2, buf);
    }

    // Epilogue: c0,c1 @ (row, col..col+1), c2,c3 @ (row+8, ...)
#pragma unroll
    for (int mi = 0; mi < 4; mi++) {
#pragma unroll
        for (int ni = 0; ni < 4; ni++) {
            int row0 = m0 + wm * 64 + mi * 16 + gr;
            int col  = n0 + wn * 32 + ni * 8 + gc * 2;
#pragma unroll
            for (int half = 0; half < 2; half++) {
                int row = row0 + half * 8;
                float v0 = acc[mi][ni][half * 2 + 0];
                float v1 = acc[mi][ni][half * 2 + 1];
                if (bias) { v0 += bias[col]; v1 += bias[col + 1]; }
                if (epi == 1) {
                    v0 = round_tf32(v0 / (1.0f + expf(-v0)));
                    v1 = round_tf32(v1 / (1.0f + expf(-v1)));
                }
                if (epi == 3) {
                    int seg = col >> 9;
                    float* dst = (seg == 0) ? Cf : (seg == 1) ? C2 : C3;
                    size_t o = (size_t)row * CC + (col & 511);
                    *(float2*)(dst + o) = make_float2(v0, v1);
                } else {
                    size_t o = (size_t)row * CC + col;
                    if (epi == 2) {
                        v0 += resid[o];
                        v1 += resid[o + 1];
                    }
                    *(float2*)(Cf + o) = make_float2(v0, v1);
                }
            }
        }
    }
}

// ---------------------------------------------------------------------------
// Fused attention, 4 batches per block: grid (16 bgroups, 8 heads).
// Output x written tf32-rounded fp32 (consumed by tf32 out-projection).
// ---------------------------------------------------------------------------
#define ATTN_SMEM (4 * 64 * 68 * 4)

__global__ __launch_bounds__(256, 1) void attn_kernel() {
    extern __shared__ float kv[];      // staging: [4][64][68]
    __shared__ float qrow[4][64];
    __shared__ float s[4][64];

    int h   = blockIdx.y;
    int bg0 = blockIdx.x * 4;
    int t   = threadIdx.x;
    int bh  = t >> 6;
    int i   = t & 63;

    float kreg[64], vreg[64];

#pragma unroll
    for (int it = 0; it < 16; it++) {
        int slot = t + it * 256;
        int b  = slot >> 10;
        int m  = (slot >> 4) & 63;
        int d4 = slot & 15;
        float4 x = *(const float4*)(g_k + ((size_t)((bg0 + b) * 64 + m)) * 512 + h * 64 + d4 * 4);
        *(float4*)&kv[(b * 64 + m) * 68 + d4 * 4] = x;
    }
    __syncthreads();
#pragma unroll
    for (int d = 0; d < 64; d++) kreg[d] = kv[(bh * 64 + i) * 68 + d];
    __syncthreads();

#pragma unroll
    for (int it = 0; it < 16; it++) {
        int slot = t + it * 256;
        int b  = slot >> 10;
        int m  = (slot >> 4) & 63;
        int d4 = slot & 15;
        float4 x = *(const float4*)(g_v + ((size_t)((bg0 + b) * 64 + m)) * 512 + h * 64 + d4 * 4);
        *(float4*)&kv[(b * 64 + m) * 68 + d4 * 4] = x;
    }
    __syncthreads();
#pragma unroll
    for (int m = 0; m < 64; m++) vreg[m] = kv[(bh * 64 + m) * 68 + i];
    __syncthreads();

    for (int n = 0; n < 64; n++) {
        if (t < 64) {
            int b = t >> 4, w = t & 15;
            float4 qv = *(const float4*)(g_q + ((size_t)((bg0 + b) * 64 + n)) * 512 + h * 64 + w * 4);
            *(float4*)&qrow[b][w * 4] = qv;
        }
        __syncthreads();

        const float* pep = g_pe + ((size_t)(n * 64 + i)) * 512 + h * 64;
        float p = 0.0f;
#pragma unroll
        for (int d4 = 0; d4 < 16; d4++) {
            float4 pe4 = *(const float4*)(pep + d4 * 4);
            int d = d4 * 4;
            p = fmaf(qrow[bh][d + 0] * kreg[d + 0], pe4.x, p);
            p = fmaf(qrow[bh][d + 1] * kreg[d + 1], pe4.y, p);
            p = fmaf(qrow[bh][d + 2] * kreg[d + 2], pe4.z, p);
            p = fmaf(qrow[bh][d + 3] * kreg[d + 3], pe4.w, p);
        }
        s[bh][i] = p * 0.125f;
        __syncthreads();

        if (t < 128) {
            int w = t >> 5, lane = t & 31;
            float a  = s[w][lane];
            float c2 = s[w][lane + 32];
            float mx = fmaxf(a, c2);
#pragma unroll
            for (int off = 16; off > 0; off >>= 1)
                mx = fmaxf(mx, __shfl_xor_sync(0xffffffffu, mx, off));
            float e1 = __expf(a - mx), e2 = __expf(c2 - mx);
            float sm = e1 + e2;
#pragma unroll
            for (int off = 16; off > 0; off >>= 1)
                sm += __shfl_xor_sync(0xffffffffu, sm, off);
            float inv = 1.0f / sm;
            s[w][lane]      = e1 * inv;
            s[w][lane + 32] = e2 * inv;
        }
        __syncthreads();

        float xv = 0.0f;
#pragma unroll
        for (int m = 0; m < 64; m++)
            xv = fmaf(s[bh][m], vreg[m], xv);
        size_t o = ((size_t)((bg0 + bh) * 64 + n)) * 512 + h * 64 + i;
        g_x[o] = round_tf32(xv);
        __syncthreads();
    }
}

// ---------------------------------------------------------------------------
// Launch — parallel branches:
//   s1: embed ─(ew)─ MLP1 ─ MLP2 ─e1─┐
//   s2: qround ─(ew)─ QKV ─e2────────┼─ attn ─ out   (main)
//   main: wconv+bias ─ew─┘
// ---------------------------------------------------------------------------
extern "C" void kernel_launch(void* const* d_in, const int* in_sizes, int n_in,
                              void* d_out, int out_size)
{
    const float* query = (const float*)d_in[0];
    const float* qpos  = (const float*)d_in[1];
    const float* Wq    = (const float*)d_in[2];
    const float* bq    = (const float*)d_in[3];
    const float* Wk    = (const float*)d_in[4];
    const float* Wv    = (const float*)d_in[5];
    const float* bv    = (const float*)d_in[6];
    const float* Wo    = (const float*)d_in[7];
    const float* bo    = (const float*)d_in[8];
    const float* W1    = (const float*)d_in[9];
    const float* b1    = (const float*)d_in[10];
    const float* W2    = (const float*)d_in[11];
    const float* b2    = (const float*)d_in[12];
    float* out = (float*)d_out;

    static cudaStream_t s1 = nullptr, s2 = nullptr;
    static cudaEvent_t e0 = nullptr, ew = nullptr, e1 = nullptr, e2 = nullptr;
    if (!s1) {
        cudaStreamCreateWithFlags(&s1, cudaStreamNonBlocking);
        cudaStreamCreateWithFlags(&s2, cudaStreamNonBlocking);
        cudaEventCreateWithFlags(&e0, cudaEventDisableTiming);
        cudaEventCreateWithFlags(&ew, cudaEventDisableTiming);
        cudaEventCreateWithFlags(&e1, cudaEventDisableTiming);
        cudaEventCreateWithFlags(&e2, cudaEventDisableTiming);
        cudaFuncSetAttribute(gemm_tf32, cudaFuncAttributeMaxDynamicSharedMemorySize, TSMEM);
        cudaFuncSetAttribute(attn_kernel, cudaFuncAttributeMaxDynamicSharedMemorySize, ATTN_SMEM);
    }

    void *p_pe, *p_q, *p_k, *p_v, *p_x, *p_bqkv, *p_emb, *p_hid, *p_qt, *p_wt;
    cudaGetSymbolAddress(&p_pe,   g_pe);
    cudaGetSymbolAddress(&p_q,    g_q);
    cudaGetSymbolAddress(&p_k,    g_k);
    cudaGetSymbolAddress(&p_v,    g_v);
    cudaGetSymbolAddress(&p_x,    g_x);
    cudaGetSymbolAddress(&p_bqkv, g_bqkv);
    cudaGetSymbolAddress(&p_emb,  g_emb);
    cudaGetSymbolAddress(&p_hid,  g_hid);
    cudaGetSymbolAddress(&p_qt,   g_qt);
    cudaGetSymbolAddress(&p_wt,   g_wt);

    const float* wt = (const float*)p_wt;
    const int WSLOT = CC * CC;

    // fork
    cudaEventRecord(e0, 0);
    cudaStreamWaitEvent(s1, e0, 0);
    cudaStreamWaitEvent(s2, e0, 0);

    // s1: embedding ; s2: query rounding (both independent of weights)
    embed_kernel<<<4096, 256, 0, s1>>>(qpos);
    qround_kernel<<<ROWS * CC / 256, 256, 0, s2>>>(query);

    // main: weight transposes + fused bias (one launch)
    wconv_all<<<dim3(16, 16, 7), 256>>>(W1, W2, Wq, Wk, Wv, Wo, bq, bv);
    cudaEventRecord(ew, 0);

    // s1: pe MLP (tf32)
    cudaStreamWaitEvent(s1, ew, 0);
    gemm_tf32<<<dim3(4, 32), 256, TSMEM, s1>>>(
        (const float*)p_emb, wt + 0 * WSLOT, b1, nullptr,
        (float*)p_hid, nullptr, nullptr, FREQE, 1);
    gemm_tf32<<<dim3(4, 32), 256, TSMEM, s1>>>(
        (const float*)p_hid, wt + 1 * WSLOT, b2, nullptr,
        (float*)p_pe, nullptr, nullptr, CC, 0);
    cudaEventRecord(e1, s1);

    // s2: fused QKV (tf32)
    cudaStreamWaitEvent(s2, ew, 0);
    gemm_tf32<<<dim3(12, 32), 256, TSMEM, s2>>>(
        (const float*)p_qt, wt + 2 * WSLOT, (const float*)p_bqkv, nullptr,
        (float*)p_q, (float*)p_k, (float*)p_v, CC, 3);
    cudaEventRecord(e2, s2);

    // join -> attention -> output projection (+bias +residual)
    cudaStreamWaitEvent(0, e1, 0);
    cudaStreamWaitEvent(0, e2, 0);
    attn_kernel<<<dim3(16, HH), 256, ATTN_SMEM>>>();
    gemm_tf32<<<dim3(4, 32), 256, TSMEM>>>(
        (const float*)p_x, wt + 5 * WSLOT, bo, query,
        out, nullptr, nullptr, CC, 2);
}